// round 3
// baseline (speedup 1.0000x reference)
#include <cuda_runtime.h>
#include <cstdint>
#include <cstddef>

// ----------------------------------------------------------------------------
// Problem constants (from reference): B=32, S=512, D=1024, F=4096,
// R_COMMON=R_DOMAIN=16, E=8, ALPHA=2. T = B*S = 16384 tokens.
// expert_ids is per-BATCH (512 consecutive tokens share an expert), so any
// 128-row M-tile has a single expert -> expert LoRA fuses into GEMM epilogue.
// ----------------------------------------------------------------------------

#define T_TOK   16384
#define D_DIM   1024
#define F_DIM   4096
#define ALPHA_F 2.0f

// Scratch (device globals: allocation-free, per harness rules)
__device__ float g_hidden[(size_t)T_TOK * F_DIM];  // 256 MB intermediate
__device__ float g_U1[T_TOK * 32];                 // stage-1 low-rank proj (ALPHA folded)
__device__ float g_U2[T_TOK * 32];                 // stage-2 low-rank proj

// ============================================================================
// Kernel 1/3: low-rank projection.
//   U[t, 0:16]  = ALPHA * X[t,:] . Wa_c[r,:]          (r = 0..15)
//   U[t,16:32]  = ALPHA * X[t,:] . Wa_e[e_t, r-16, :]
// Block: 256 threads, 8 tokens per block. K processed in 1024-wide chunks.
// Thread (r,sub): r = tid>>3 selects output row, sub = tid&7 covers an
// interleaved 1/8 slice of K (float4 granularity -> conflict-free LDS.128).
// ============================================================================
__global__ __launch_bounds__(256) void lora_proj_kernel(
    const float* __restrict__ X,      // [T, K]
    const float* __restrict__ Wa_c,   // [16, K]
    const float* __restrict__ Wa_e,   // [E, 16, K]
    const int*   __restrict__ expert_ids,
    float*       __restrict__ U,      // [T, 32]
    int K)
{
    __shared__ float xs[8][1024];

    const int tid = threadIdx.x;
    const int t0  = blockIdx.x * 8;
    const int e   = expert_ids[t0 >> 9];          // t0/512 = batch index
    const int r   = tid >> 3;                     // 0..31
    const int sub = tid & 7;                      // 0..7

    const float* wrow = (r < 16)
        ? (Wa_c + (size_t)r * K)
        : (Wa_e + ((size_t)e * 16 + (r - 16)) * (size_t)K);

    float acc[8];
#pragma unroll
    for (int tt = 0; tt < 8; tt++) acc[tt] = 0.0f;

    for (int kc = 0; kc < K; kc += 1024) {
        __syncthreads();  // protect xs from previous chunk's readers
        // stage 8 token rows x 1024 floats = 2048 float4, 8 per thread
#pragma unroll
        for (int i = 0; i < 8; i++) {
            int f  = tid + i * 256;   // 0..2047
            int tt = f >> 8;          // token within block
            int c4 = f & 255;         // float4 column
            *(float4*)&xs[tt][c4 * 4] =
                *(const float4*)(X + (size_t)(t0 + tt) * K + kc + c4 * 4);
        }
        __syncthreads();

        const float4* w4 = (const float4*)(wrow + kc);
#pragma unroll 4
        for (int i = 0; i < 32; i++) {
            int f = i * 8 + sub;                 // interleaved slice
            float4 w = w4[f];
#pragma unroll
            for (int tt = 0; tt < 8; tt++) {
                float4 xv = *(const float4*)&xs[tt][f * 4];
                acc[tt] += w.x * xv.x + w.y * xv.y + w.z * xv.z + w.w * xv.w;
            }
        }
    }

    // reduce across the 8 sub-lanes (contiguous lane groups of 8)
#pragma unroll
    for (int off = 4; off > 0; off >>= 1)
#pragma unroll
        for (int tt = 0; tt < 8; tt++)
            acc[tt] += __shfl_down_sync(0xffffffffu, acc[tt], off, 8);

    if (sub == 0) {
#pragma unroll
        for (int tt = 0; tt < 8; tt++)
            U[(size_t)(t0 + tt) * 32 + r] = ALPHA_F * acc[tt];
    }
}

// ============================================================================
// Kernel 2/4: main GEMM + fused rank-32 LoRA epilogue (+ optional ReLU).
//   C[m,n] = sum_k A[m,k]*B[n,k]
//          + sum_{r<16} U[m,r]   * Wb_c[n,r]
//          + sum_{r<16} U[m,16+r]* Wb_e[e, n, r]
// 128x128 block tile, BK=16, 256 threads, 8x8 microtile. All dims are
// multiples of 128 -> no bounds checks.
// ============================================================================
#define BM 128
#define BN 128
#define BK 16
#define TM 8
#define TN 8
#define LDA (BM + 4)   // padded smem stride (132) -> conflict-mitigated

__device__ __forceinline__ void load_tile(
    float S[BK][LDA], const float* __restrict__ P,
    size_t ld, int row0, int k0, int tid)
{
    // tile = 128 rows x 16 cols = 512 float4; 2 per thread
#pragma unroll
    for (int i = 0; i < 2; i++) {
        int f  = tid + i * 256;
        int r  = f >> 2;
        int c4 = f & 3;
        float4 v = *(const float4*)(P + (size_t)(row0 + r) * ld + k0 + c4 * 4);
        S[c4 * 4 + 0][r] = v.x;
        S[c4 * 4 + 1][r] = v.y;
        S[c4 * 4 + 2][r] = v.z;
        S[c4 * 4 + 3][r] = v.w;
    }
}

__device__ __forceinline__ void compute_tile(
    float acc[TM][TN], const float As[BK][LDA], const float Bs[BK][LDA],
    int ty, int tx)
{
#pragma unroll
    for (int k = 0; k < BK; k++) {
        float a[TM], b[TN];
        *(float4*)&a[0] = *(const float4*)&As[k][ty * TM];
        *(float4*)&a[4] = *(const float4*)&As[k][ty * TM + 4];
        *(float4*)&b[0] = *(const float4*)&Bs[k][tx * TN];
        *(float4*)&b[4] = *(const float4*)&Bs[k][tx * TN + 4];
#pragma unroll
        for (int i = 0; i < TM; i++)
#pragma unroll
            for (int j = 0; j < TN; j++)
                acc[i][j] += a[i] * b[j];
    }
}

__global__ __launch_bounds__(256, 2) void gemm_lora_kernel(
    const float* __restrict__ A,     // [M, K]
    const float* __restrict__ B,     // [N, K]
    const float* __restrict__ U,     // [M, 32] (ALPHA folded)
    const float* __restrict__ Wb_c,  // [N, 16]
    const float* __restrict__ Wb_e,  // [E, N, 16]
    const int*   __restrict__ expert_ids,
    float*       __restrict__ C,     // [M, N]
    int N, int K, int do_relu)
{
    __shared__ float As[BK][LDA];
    __shared__ float Bs[BK][LDA];

    const int tid = threadIdx.x;
    const int m0  = blockIdx.y * BM;
    const int n0  = blockIdx.x * BN;
    const int e   = expert_ids[m0 >> 9];   // tile never crosses a batch
    const int tx  = tid & 15;
    const int ty  = tid >> 4;

    float acc[TM][TN];
#pragma unroll
    for (int i = 0; i < TM; i++)
#pragma unroll
        for (int j = 0; j < TN; j++) acc[i][j] = 0.0f;

    // ---- main K loop ----
    for (int kt = 0; kt < K; kt += BK) {
        load_tile(As, A, (size_t)K, m0, kt, tid);
        load_tile(Bs, B, (size_t)K, n0, kt, tid);
        __syncthreads();
        compute_tile(acc, As, Bs, ty, tx);
        __syncthreads();
    }

    // ---- LoRA epilogue: common (r 0..15) then expert (r 16..31) ----
    load_tile(As, U, 32, m0, 0, tid);
    load_tile(Bs, Wb_c, 16, n0, 0, tid);
    __syncthreads();
    compute_tile(acc, As, Bs, ty, tx);
    __syncthreads();

    load_tile(As, U, 32, m0, 16, tid);
    load_tile(Bs, Wb_e + (size_t)e * N * 16, 16, n0, 0, tid);
    __syncthreads();
    compute_tile(acc, As, Bs, ty, tx);

    // ---- store (optional ReLU) ----
#pragma unroll
    for (int i = 0; i < TM; i++) {
        int row = m0 + ty * TM + i;
        float* cp = C + (size_t)row * N + n0 + tx * TN;
        float4 v0, v1;
        v0.x = acc[i][0]; v0.y = acc[i][1]; v0.z = acc[i][2]; v0.w = acc[i][3];
        v1.x = acc[i][4]; v1.y = acc[i][5]; v1.z = acc[i][6]; v1.w = acc[i][7];
        if (do_relu) {
            v0.x = fmaxf(v0.x, 0.f); v0.y = fmaxf(v0.y, 0.f);
            v0.z = fmaxf(v0.z, 0.f); v0.w = fmaxf(v0.w, 0.f);
            v1.x = fmaxf(v1.x, 0.f); v1.y = fmaxf(v1.y, 0.f);
            v1.z = fmaxf(v1.z, 0.f); v1.w = fmaxf(v1.w, 0.f);
        }
        *(float4*)cp       = v0;
        *(float4*)(cp + 4) = v1;
    }
}

// ============================================================================
// Launch: 4 kernels on the capture stream.
//   1) U1 = ALPHA * [x@common_wi_a^T | x@experts_wi_a[e]^T]          (T x 32)
//   2) hidden = relu(x@wi^T + U1@[common_wi_b|experts_wi_b[e]]^T)    (T x F)
//   3) U2 = ALPHA * [h@common_wo_a^T | h@experts_wo_a[e]^T]          (T x 32)
//   4) out = h@wo^T + U2@[common_wo_b|experts_wo_b[e]]^T             (T x D)
// ============================================================================
extern "C" void kernel_launch(void* const* d_in, const int* in_sizes, int n_in,
                              void* d_out, int out_size)
{
    (void)in_sizes; (void)n_in; (void)out_size;

    const float* x      = (const float*)d_in[0];   // [B,S,D]
    const int*   eids   = (const int*)  d_in[1];   // [B]
    const float* wi     = (const float*)d_in[2];   // [F,D]
    const float* wo     = (const float*)d_in[3];   // [D,F]
    const float* cwi_a  = (const float*)d_in[4];   // [16,D]
    const float* cwi_b  = (const float*)d_in[5];   // [F,16]
    const float* cwo_a  = (const float*)d_in[6];   // [16,F]
    const float* cwo_b  = (const float*)d_in[7];   // [D,16]
    const float* ewi_a  = (const float*)d_in[8];   // [E,16,D]
    const float* ewi_b  = (const float*)d_in[9];   // [E,F,16]
    const float* ewo_a  = (const float*)d_in[10];  // [E,16,F]
    const float* ewo_b  = (const float*)d_in[11];  // [E,D,16]
    float*       out    = (float*)d_out;           // [B,S,D]

    float *hidden, *U1, *U2;
    cudaGetSymbolAddress((void**)&hidden, g_hidden);
    cudaGetSymbolAddress((void**)&U1, g_U1);
    cudaGetSymbolAddress((void**)&U2, g_U2);

    // Stage 1 low-rank projection: K = D = 1024
    lora_proj_kernel<<<T_TOK / 8, 256>>>(x, cwi_a, ewi_a, eids, U1, D_DIM);

    // Stage 1 GEMM: M=T, N=F, K=D, ReLU
    {
        dim3 grid(F_DIM / BN, T_TOK / BM);
        gemm_lora_kernel<<<grid, 256>>>(x, wi, U1, cwi_b, ewi_b, eids,
                                        hidden, F_DIM, D_DIM, 1);
    }

    // Stage 2 low-rank projection: K = F = 4096
    lora_proj_kernel<<<T_TOK / 8, 256>>>(hidden, cwo_a, ewo_a, eids, U2, F_DIM);

    // Stage 2 GEMM: M=T, N=D, K=F, no ReLU
    {
        dim3 grid(D_DIM / BN, T_TOK / BM);
        gemm_lora_kernel<<<grid, 256>>>(hidden, wo, U2, cwo_b, ewo_b, eids,
                                        out, D_DIM, F_DIM, 0);
    }
}

// round 4
// speedup vs baseline: 1.0003x; 1.0003x over previous
#include <cuda_runtime.h>
#include <cstdint>
#include <cstddef>

// ----------------------------------------------------------------------------
// Problem constants (from reference): B=32, S=512, D=1024, F=4096,
// R_COMMON=R_DOMAIN=16, E=8, ALPHA=2. T = B*S = 16384 tokens.
// expert_ids is per-BATCH (512 consecutive tokens share an expert), so any
// 128-row M-tile has a single expert -> expert LoRA fuses into GEMM epilogue.
// ----------------------------------------------------------------------------

#define T_TOK   16384
#define D_DIM   1024
#define F_DIM   4096
#define ALPHA_F 2.0f

// Scratch (device globals: allocation-free, per harness rules)
__device__ float g_hidden[(size_t)T_TOK * F_DIM];  // 256 MB intermediate
__device__ float g_U1[T_TOK * 32];                 // stage-1 low-rank proj (ALPHA folded)
__device__ float g_U2[T_TOK * 32];                 // stage-2 low-rank proj

// ============================================================================
// Kernel 1/3: low-rank projection.
//   U[t, 0:16]  = ALPHA * X[t,:] . Wa_c[r,:]          (r = 0..15)
//   U[t,16:32]  = ALPHA * X[t,:] . Wa_e[e_t, r-16, :]
// Block: 256 threads, 8 tokens per block. K processed in 1024-wide chunks.
// Thread (r,sub): r = tid>>3 selects output row, sub = tid&7 covers an
// interleaved 1/8 slice of K (float4 granularity -> conflict-free LDS.128).
// ============================================================================
__global__ __launch_bounds__(256) void lora_proj_kernel(
    const float* __restrict__ X,      // [T, K]
    const float* __restrict__ Wa_c,   // [16, K]
    const float* __restrict__ Wa_e,   // [E, 16, K]
    const int*   __restrict__ expert_ids,
    float*       __restrict__ U,      // [T, 32]
    int K)
{
    __shared__ float xs[8][1024];

    const int tid = threadIdx.x;
    const int t0  = blockIdx.x * 8;
    const int e   = expert_ids[t0 >> 9];          // t0/512 = batch index
    const int r   = tid >> 3;                     // 0..31
    const int sub = tid & 7;                      // 0..7

    const float* wrow = (r < 16)
        ? (Wa_c + (size_t)r * K)
        : (Wa_e + ((size_t)e * 16 + (r - 16)) * (size_t)K);

    float acc[8];
#pragma unroll
    for (int tt = 0; tt < 8; tt++) acc[tt] = 0.0f;

    for (int kc = 0; kc < K; kc += 1024) {
        __syncthreads();  // protect xs from previous chunk's readers
        // stage 8 token rows x 1024 floats = 2048 float4, 8 per thread
#pragma unroll
        for (int i = 0; i < 8; i++) {
            int f  = tid + i * 256;   // 0..2047
            int tt = f >> 8;          // token within block
            int c4 = f & 255;         // float4 column
            *(float4*)&xs[tt][c4 * 4] =
                *(const float4*)(X + (size_t)(t0 + tt) * K + kc + c4 * 4);
        }
        __syncthreads();

        const float4* w4 = (const float4*)(wrow + kc);
#pragma unroll 4
        for (int i = 0; i < 32; i++) {
            int f = i * 8 + sub;                 // interleaved slice
            float4 w = w4[f];
#pragma unroll
            for (int tt = 0; tt < 8; tt++) {
                float4 xv = *(const float4*)&xs[tt][f * 4];
                acc[tt] += w.x * xv.x + w.y * xv.y + w.z * xv.z + w.w * xv.w;
            }
        }
    }

    // reduce across the 8 sub-lanes (contiguous lane groups of 8)
#pragma unroll
    for (int off = 4; off > 0; off >>= 1)
#pragma unroll
        for (int tt = 0; tt < 8; tt++)
            acc[tt] += __shfl_down_sync(0xffffffffu, acc[tt], off, 8);

    if (sub == 0) {
#pragma unroll
        for (int tt = 0; tt < 8; tt++)
            U[(size_t)(t0 + tt) * 32 + r] = ALPHA_F * acc[tt];
    }
}

// ============================================================================
// Kernel 2/4: main GEMM + fused rank-32 LoRA epilogue (+ optional ReLU).
//   C[m,n] = sum_k A[m,k]*B[n,k]
//          + sum_{r<16} U[m,r]   * Wb_c[n,r]
//          + sum_{r<16} U[m,16+r]* Wb_e[e, n, r]
// 128x128 block tile, BK=16, 256 threads, 8x8 microtile. All dims are
// multiples of 128 -> no bounds checks.
// ============================================================================
#define BM 128
#define BN 128
#define BK 16
#define TM 8
#define TN 8
#define LDA (BM + 4)   // padded smem stride (132) -> conflict-mitigated

__device__ __forceinline__ void load_tile(
    float S[BK][LDA], const float* __restrict__ P,
    size_t ld, int row0, int k0, int tid)
{
    // tile = 128 rows x 16 cols = 512 float4; 2 per thread
#pragma unroll
    for (int i = 0; i < 2; i++) {
        int f  = tid + i * 256;
        int r  = f >> 2;
        int c4 = f & 3;
        float4 v = *(const float4*)(P + (size_t)(row0 + r) * ld + k0 + c4 * 4);
        S[c4 * 4 + 0][r] = v.x;
        S[c4 * 4 + 1][r] = v.y;
        S[c4 * 4 + 2][r] = v.z;
        S[c4 * 4 + 3][r] = v.w;
    }
}

__device__ __forceinline__ void compute_tile(
    float acc[TM][TN], const float As[BK][LDA], const float Bs[BK][LDA],
    int ty, int tx)
{
#pragma unroll
    for (int k = 0; k < BK; k++) {
        float a[TM], b[TN];
        *(float4*)&a[0] = *(const float4*)&As[k][ty * TM];
        *(float4*)&a[4] = *(const float4*)&As[k][ty * TM + 4];
        *(float4*)&b[0] = *(const float4*)&Bs[k][tx * TN];
        *(float4*)&b[4] = *(const float4*)&Bs[k][tx * TN + 4];
#pragma unroll
        for (int i = 0; i < TM; i++)
#pragma unroll
            for (int j = 0; j < TN; j++)
                acc[i][j] += a[i] * b[j];
    }
}

__global__ __launch_bounds__(256, 2) void gemm_lora_kernel(
    const float* __restrict__ A,     // [M, K]
    const float* __restrict__ B,     // [N, K]
    const float* __restrict__ U,     // [M, 32] (ALPHA folded)
    const float* __restrict__ Wb_c,  // [N, 16]
    const float* __restrict__ Wb_e,  // [E, N, 16]
    const int*   __restrict__ expert_ids,
    float*       __restrict__ C,     // [M, N]
    int N, int K, int do_relu)
{
    __shared__ float As[BK][LDA];
    __shared__ float Bs[BK][LDA];

    const int tid = threadIdx.x;
    const int m0  = blockIdx.y * BM;
    const int n0  = blockIdx.x * BN;
    const int e   = expert_ids[m0 >> 9];   // tile never crosses a batch
    const int tx  = tid & 15;
    const int ty  = tid >> 4;

    float acc[TM][TN];
#pragma unroll
    for (int i = 0; i < TM; i++)
#pragma unroll
        for (int j = 0; j < TN; j++) acc[i][j] = 0.0f;

    // ---- main K loop ----
    for (int kt = 0; kt < K; kt += BK) {
        load_tile(As, A, (size_t)K, m0, kt, tid);
        load_tile(Bs, B, (size_t)K, n0, kt, tid);
        __syncthreads();
        compute_tile(acc, As, Bs, ty, tx);
        __syncthreads();
    }

    // ---- LoRA epilogue: common (r 0..15) then expert (r 16..31) ----
    load_tile(As, U, 32, m0, 0, tid);
    load_tile(Bs, Wb_c, 16, n0, 0, tid);
    __syncthreads();
    compute_tile(acc, As, Bs, ty, tx);
    __syncthreads();

    load_tile(As, U, 32, m0, 16, tid);
    load_tile(Bs, Wb_e + (size_t)e * N * 16, 16, n0, 0, tid);
    __syncthreads();
    compute_tile(acc, As, Bs, ty, tx);

    // ---- store (optional ReLU) ----
#pragma unroll
    for (int i = 0; i < TM; i++) {
        int row = m0 + ty * TM + i;
        float* cp = C + (size_t)row * N + n0 + tx * TN;
        float4 v0, v1;
        v0.x = acc[i][0]; v0.y = acc[i][1]; v0.z = acc[i][2]; v0.w = acc[i][3];
        v1.x = acc[i][4]; v1.y = acc[i][5]; v1.z = acc[i][6]; v1.w = acc[i][7];
        if (do_relu) {
            v0.x = fmaxf(v0.x, 0.f); v0.y = fmaxf(v0.y, 0.f);
            v0.z = fmaxf(v0.z, 0.f); v0.w = fmaxf(v0.w, 0.f);
            v1.x = fmaxf(v1.x, 0.f); v1.y = fmaxf(v1.y, 0.f);
            v1.z = fmaxf(v1.z, 0.f); v1.w = fmaxf(v1.w, 0.f);
        }
        *(float4*)cp       = v0;
        *(float4*)(cp + 4) = v1;
    }
}

// ============================================================================
// Launch: 4 kernels on the capture stream.
//   1) U1 = ALPHA * [x@common_wi_a^T | x@experts_wi_a[e]^T]          (T x 32)
//   2) hidden = relu(x@wi^T + U1@[common_wi_b|experts_wi_b[e]]^T)    (T x F)
//   3) U2 = ALPHA * [h@common_wo_a^T | h@experts_wo_a[e]^T]          (T x 32)
//   4) out = h@wo^T + U2@[common_wo_b|experts_wo_b[e]]^T             (T x D)
// ============================================================================
extern "C" void kernel_launch(void* const* d_in, const int* in_sizes, int n_in,
                              void* d_out, int out_size)
{
    (void)in_sizes; (void)n_in; (void)out_size;

    const float* x      = (const float*)d_in[0];   // [B,S,D]
    const int*   eids   = (const int*)  d_in[1];   // [B]
    const float* wi     = (const float*)d_in[2];   // [F,D]
    const float* wo     = (const float*)d_in[3];   // [D,F]
    const float* cwi_a  = (const float*)d_in[4];   // [16,D]
    const float* cwi_b  = (const float*)d_in[5];   // [F,16]
    const float* cwo_a  = (const float*)d_in[6];   // [16,F]
    const float* cwo_b  = (const float*)d_in[7];   // [D,16]
    const float* ewi_a  = (const float*)d_in[8];   // [E,16,D]
    const float* ewi_b  = (const float*)d_in[9];   // [E,F,16]
    const float* ewo_a  = (const float*)d_in[10];  // [E,16,F]
    const float* ewo_b  = (const float*)d_in[11];  // [E,D,16]
    float*       out    = (float*)d_out;           // [B,S,D]

    float *hidden, *U1, *U2;
    cudaGetSymbolAddress((void**)&hidden, g_hidden);
    cudaGetSymbolAddress((void**)&U1, g_U1);
    cudaGetSymbolAddress((void**)&U2, g_U2);

    // Stage 1 low-rank projection: K = D = 1024
    lora_proj_kernel<<<T_TOK / 8, 256>>>(x, cwi_a, ewi_a, eids, U1, D_DIM);

    // Stage 1 GEMM: M=T, N=F, K=D, ReLU
    {
        dim3 grid(F_DIM / BN, T_TOK / BM);
        gemm_lora_kernel<<<grid, 256>>>(x, wi, U1, cwi_b, ewi_b, eids,
                                        hidden, F_DIM, D_DIM, 1);
    }

    // Stage 2 low-rank projection: K = F = 4096
    lora_proj_kernel<<<T_TOK / 8, 256>>>(hidden, cwo_a, ewo_a, eids, U2, F_DIM);

    // Stage 2 GEMM: M=T, N=D, K=F, no ReLU
    {
        dim3 grid(D_DIM / BN, T_TOK / BM);
        gemm_lora_kernel<<<grid, 256>>>(hidden, wo, U2, cwo_b, ewo_b, eids,
                                        out, D_DIM, F_DIM, 0);
    }
}

// round 7
// speedup vs baseline: 1.6468x; 1.6463x over previous
#include <cuda_runtime.h>
#include <cuda_bf16.h>
#include <cstdint>
#include <cstddef>

#define T_TOK 16384
#define D_DIM 1024
#define F_DIM 4096
#define ALPHA_F 2.0f

__device__ __nv_bfloat16 g_hid_hi[(size_t)T_TOK * F_DIM];
__device__ __nv_bfloat16 g_hid_lo[(size_t)T_TOK * F_DIM];
__device__ float g_U1[T_TOK * 32];
__device__ float g_U2[T_TOK * 32];

// ---------------- helpers ----------------
__device__ __forceinline__ uint32_t smem_u32(const void* p) {
    uint32_t a;
    asm("{ .reg .u64 t; cvta.to.shared.u64 t, %1; cvt.u32.u64 %0, t; }" : "=r"(a) : "l"(p));
    return a;
}
__device__ __forceinline__ void ldsm_x4(uint32_t* r, uint32_t addr) {
    asm volatile("ldmatrix.sync.aligned.m8n8.x4.shared.b16 {%0,%1,%2,%3}, [%4];"
                 : "=r"(r[0]), "=r"(r[1]), "=r"(r[2]), "=r"(r[3]) : "r"(addr));
}
// B fragment: smem layout is [n][k] (k contiguous) == col-major KxN, so the
// m16n8k16 B fragment (consecutive k at fixed n) loads with NON-trans x2.
__device__ __forceinline__ void ldsm_x2(uint32_t* r, uint32_t addr) {
    asm volatile("ldmatrix.sync.aligned.m8n8.x2.shared.b16 {%0,%1}, [%2];"
                 : "=r"(r[0]), "=r"(r[1]) : "r"(addr));
}
__device__ __forceinline__ void mma_bf16(float* d, const uint32_t* a, const uint32_t* b) {
    asm volatile(
        "mma.sync.aligned.m16n8k16.row.col.f32.bf16.bf16.f32 "
        "{%0,%1,%2,%3},{%4,%5,%6,%7},{%8,%9},{%0,%1,%2,%3};"
        : "+f"(d[0]), "+f"(d[1]), "+f"(d[2]), "+f"(d[3])
        : "r"(a[0]), "r"(a[1]), "r"(a[2]), "r"(a[3]), "r"(b[0]), "r"(b[1]));
}

// split 16 fp32 -> bf16 hi/lo, SW128-swizzled store (rows of 128B = 64 bf16)
__device__ __forceinline__ void stage16f(char* th, char* tl, int row, int c0, const float* a) {
#pragma unroll
    for (int u = 0; u < 2; u++) {
        uint32_t hw[4], lw[4];
#pragma unroll
        for (int j = 0; j < 4; j++) {
            float x0 = a[u * 8 + 2 * j], x1 = a[u * 8 + 2 * j + 1];
            __nv_bfloat16 h0 = __float2bfloat16(x0), h1 = __float2bfloat16(x1);
            __nv_bfloat16 l0 = __float2bfloat16(x0 - __bfloat162float(h0));
            __nv_bfloat16 l1 = __float2bfloat16(x1 - __bfloat162float(h1));
            __nv_bfloat162 ph{h0, h1}, pl{l0, l1};
            hw[j] = *reinterpret_cast<uint32_t*>(&ph);
            lw[j] = *reinterpret_cast<uint32_t*>(&pl);
        }
        uint32_t off = (uint32_t)row * 128 + (uint32_t)c0 * 2 + u * 16;
        uint32_t sw = off ^ ((off >> 3) & 0x70);
        *reinterpret_cast<uint4*>(th + sw) = make_uint4(hw[0], hw[1], hw[2], hw[3]);
        *reinterpret_cast<uint4*>(tl + sw) = make_uint4(lw[0], lw[1], lw[2], lw[3]);
    }
}

// ================= low-rank projection (U = ALPHA * X . Wa^T) =================
template <int BF>
__global__ __launch_bounds__(256) void lora_proj(
    const float* __restrict__ Xf, const __nv_bfloat16* __restrict__ Xhi,
    const __nv_bfloat16* __restrict__ Xlo,
    const float* __restrict__ Wa_c, const float* __restrict__ Wa_e,
    const int* __restrict__ eids, float* __restrict__ U, int K)
{
    __shared__ float xs[8][1024];
    const int tid = threadIdx.x, t0 = blockIdx.x * 8;
    const int e = eids[t0 >> 9];
    const int r = tid >> 3, sub = tid & 7;
    const float* wrow = (r < 16) ? (Wa_c + (size_t)r * K)
                                 : (Wa_e + ((size_t)e * 16 + (r - 16)) * (size_t)K);
    float acc[8];
#pragma unroll
    for (int t = 0; t < 8; t++) acc[t] = 0.f;

    for (int kc = 0; kc < K; kc += 1024) {
        __syncthreads();
        if (BF) {
#pragma unroll
            for (int i = 0; i < 4; i++) {
                int f = tid + i * 256, tt = f >> 7, c8 = f & 127;
                size_t g = (size_t)(t0 + tt) * K + kc + c8 * 8;
                uint4 h = *(const uint4*)(Xhi + g), l = *(const uint4*)(Xlo + g);
                const uint32_t* hw = (const uint32_t*)&h;
                const uint32_t* lw = (const uint32_t*)&l;
#pragma unroll
                for (int w = 0; w < 4; w++) {
                    float2 fh = __bfloat1622float2(*(const __nv_bfloat162*)&hw[w]);
                    float2 fl = __bfloat1622float2(*(const __nv_bfloat162*)&lw[w]);
                    xs[tt][c8 * 8 + w * 2] = fh.x + fl.x;
                    xs[tt][c8 * 8 + w * 2 + 1] = fh.y + fl.y;
                }
            }
        } else {
#pragma unroll
            for (int i = 0; i < 8; i++) {
                int f = tid + i * 256, tt = f >> 8, c4 = f & 255;
                *(float4*)&xs[tt][c4 * 4] =
                    *(const float4*)(Xf + (size_t)(t0 + tt) * K + kc + c4 * 4);
            }
        }
        __syncthreads();
        const float4* w4 = (const float4*)(wrow + kc);
#pragma unroll 4
        for (int i = 0; i < 32; i++) {
            int f = i * 8 + sub;
            float4 w = w4[f];
#pragma unroll
            for (int t = 0; t < 8; t++) {
                float4 xv = *(const float4*)&xs[t][f * 4];
                acc[t] += w.x * xv.x + w.y * xv.y + w.z * xv.z + w.w * xv.w;
            }
        }
    }
#pragma unroll
    for (int off = 4; off > 0; off >>= 1)
#pragma unroll
        for (int t = 0; t < 8; t++) acc[t] += __shfl_down_sync(0xffffffffu, acc[t], off, 8);
    if (sub == 0)
#pragma unroll
        for (int t = 0; t < 8; t++) U[(size_t)(t0 + t) * 32 + r] = ALPHA_F * acc[t];
}

// ================== mma.sync split-bf16 GEMM + fused LoRA ==================
// Tile 128x128, BK=64. smem stage = Ahi,Alo,Bhi,Blo (16KB each) = 64KB; x2.
// MODE 1: A = fp32 x, out = relu -> bf16 hi/lo.  MODE 0: A = bf16 hi/lo, out fp32.
#define STG 65536
#define SMEM_DYN (2 * STG + 1024)

template <int MODE>
__global__ __launch_bounds__(256, 1) void gemm_mma(
    const float* __restrict__ Af,
    const __nv_bfloat16* __restrict__ Ahi_g, const __nv_bfloat16* __restrict__ Alo_g,
    const float* __restrict__ Bw, const float* __restrict__ U,
    const float* __restrict__ Wbc, const float* __restrict__ Wbe,
    const int* __restrict__ eids,
    float* __restrict__ outF, __nv_bfloat16* __restrict__ outHi,
    __nv_bfloat16* __restrict__ outLo, int N, int K)
{
    extern __shared__ char smraw[];
    uint32_t sd0 = smem_u32(smraw);
    char* smem = smraw + (((sd0 + 1023u) & ~1023u) - sd0);

    const int tid = threadIdx.x, wid = tid >> 5, lane = tid & 31;
    const int m0 = blockIdx.y * 128, n0 = blockIdx.x * 128;
    const int e = eids[m0 >> 9];

    // staging map: each thread owns one (row, 32-col half)
    const int srow = tid >> 1, hf = tid & 1;

    // warp tile: 2 warps along M (64 each), 4 along N (32 each)
    const int m_w = (wid >> 2) * 64, n_w = (wid & 3) * 32;

    // ldmatrix per-lane addressing (swizzle mask is constant per row)
    const int arow = lane & 15;                 // A row within m16 tile
    const int ac8 = (lane >> 4) * 16;           // A k-half byte offset (8 bf16)
    const int brow = lane & 7;                  // B row (n) within n8 tile
    const int bc8 = ((lane >> 3) & 1) * 16;     // B k-half byte offset (x2: lanes 0-15)

    float acc[4][4][4];
#pragma unroll
    for (int i = 0; i < 4; i++)
#pragma unroll
        for (int j = 0; j < 4; j++)
#pragma unroll
            for (int q = 0; q < 4; q++) acc[i][j][q] = 0.f;

    const int KCH = K >> 6, NCH = KCH + 1;

    float aR[32], bR[32];
    uint4 hR[4], lR[4];

    // ---- register prefetch of chunk ch ----
    auto load_regs = [&](int ch) {
        if (ch < KCH) {
            const int kc = ch << 6, c0 = hf * 32;
            if (MODE == 1) {
                const float* s = Af + (size_t)(m0 + srow) * K + kc + c0;
#pragma unroll
                for (int i = 0; i < 8; i++) *(float4*)&aR[i * 4] = *(const float4*)(s + i * 4);
            } else {
                size_t g = (size_t)(m0 + srow) * K + kc + c0;
#pragma unroll
                for (int j = 0; j < 4; j++) {
                    hR[j] = *(const uint4*)(Ahi_g + g + j * 8);
                    lR[j] = *(const uint4*)(Alo_g + g + j * 8);
                }
            }
            const float* sb = Bw + (size_t)(n0 + srow) * K + kc + c0;
#pragma unroll
            for (int i = 0; i < 8; i++) *(float4*)&bR[i * 4] = *(const float4*)(sb + i * 4);
        } else {  // LoRA chunk: A = U[m,0:32]; B cols 0:16 = Wbc, 16:32 = Wbe[e]
            const int c0 = hf * 16;
            const float* su = U + (size_t)(m0 + srow) * 32 + c0;
#pragma unroll
            for (int i = 0; i < 4; i++) *(float4*)&aR[i * 4] = *(const float4*)(su + i * 4);
            const float* sb = hf ? (Wbe + (size_t)e * N * 16 + (size_t)(n0 + srow) * 16)
                                 : (Wbc + (size_t)(n0 + srow) * 16);
#pragma unroll
            for (int i = 0; i < 4; i++) *(float4*)&bR[i * 4] = *(const float4*)(sb + i * 4);
        }
    };

    // ---- store prefetched regs into smem stage s ----
    auto store_stage = [&](int ch, int s) {
        char* sA_hi = smem + s * STG;
        char* sA_lo = sA_hi + 16384;
        char* sB_hi = sA_hi + 32768;
        char* sB_lo = sA_hi + 49152;
        if (ch < KCH) {
            const int c0 = hf * 32;
            if (MODE == 1) {
                stage16f(sA_hi, sA_lo, srow, c0, aR);
                stage16f(sA_hi, sA_lo, srow, c0 + 16, aR + 16);
            } else {
#pragma unroll
                for (int j = 0; j < 4; j++) {
                    uint32_t off = (uint32_t)srow * 128 + c0 * 2 + j * 16;
                    uint32_t sw = off ^ ((off >> 3) & 0x70);
                    *(uint4*)(sA_hi + sw) = hR[j];
                    *(uint4*)(sA_lo + sw) = lR[j];
                }
            }
            stage16f(sB_hi, sB_lo, srow, c0, bR);
            stage16f(sB_hi, sB_lo, srow, c0 + 16, bR + 16);
        } else {
            const int c0 = hf * 16;
            stage16f(sA_hi, sA_lo, srow, c0, aR);
            stage16f(sB_hi, sB_lo, srow, c0, bR);
        }
    };

    // ---- MMA over smem stage s ----
    auto compute_stage = [&](int s, int nks) {
        uint32_t Abase = smem_u32(smem) + s * STG;
        uint32_t Bbase = Abase + 32768;
#pragma unroll
        for (int ks = 0; ks < 4; ks++) {
            if (ks >= nks) break;
            const int kb = ks * 32;  // byte offset of this k16 (16 bf16 = 32B)
            uint32_t ahi[4][4], alo[4][4], bhi[4][2], blo[4][2];
#pragma unroll
            for (int mi = 0; mi < 4; mi++) {
                int row = m_w + mi * 16 + arow;
                uint32_t ro = (uint32_t)row * 128, xm = (uint32_t)(row & 7) << 4;
                uint32_t col = (uint32_t)(kb + ac8) ^ xm;
                ldsm_x4(ahi[mi], Abase + ro + col);
                ldsm_x4(alo[mi], Abase + 16384 + ro + col);
            }
#pragma unroll
            for (int ni = 0; ni < 4; ni++) {
                int row = n_w + ni * 8 + brow;
                uint32_t ro = (uint32_t)row * 128, xm = (uint32_t)(row & 7) << 4;
                uint32_t col = (uint32_t)(kb + bc8) ^ xm;
                ldsm_x2(bhi[ni], Bbase + ro + col);
                ldsm_x2(blo[ni], Bbase + 16384 + ro + col);
            }
#pragma unroll
            for (int mi = 0; mi < 4; mi++)
#pragma unroll
                for (int ni = 0; ni < 4; ni++) {
                    mma_bf16(acc[mi][ni], ahi[mi], bhi[ni]);
                    mma_bf16(acc[mi][ni], ahi[mi], blo[ni]);
                    mma_bf16(acc[mi][ni], alo[mi], bhi[ni]);
                }
        }
    };

    // ---- pipelined mainloop ----
    load_regs(0);
    store_stage(0, 0);
    __syncthreads();
    for (int ch = 0; ch < NCH; ch++) {
        if (ch + 1 < NCH) load_regs(ch + 1);
        compute_stage(ch & 1, (ch < KCH) ? 4 : 2);
        __syncthreads();
        if (ch + 1 < NCH) {
            store_stage(ch + 1, (ch + 1) & 1);
            __syncthreads();
        }
    }

    // ---- epilogue ----
    const int er = lane >> 2, ec = (lane & 3) * 2;
#pragma unroll
    for (int mi = 0; mi < 4; mi++) {
#pragma unroll
        for (int ni = 0; ni < 4; ni++) {
            float* d = acc[mi][ni];
            int gr0 = m0 + m_w + mi * 16 + er;
            int gc = n0 + n_w + ni * 8 + ec;
            if (MODE == 1) {
#pragma unroll
                for (int hrow = 0; hrow < 2; hrow++) {
                    int gr = gr0 + hrow * 8;
                    float v0 = fmaxf(d[hrow * 2], 0.f), v1 = fmaxf(d[hrow * 2 + 1], 0.f);
                    __nv_bfloat16 h0 = __float2bfloat16(v0), h1 = __float2bfloat16(v1);
                    __nv_bfloat16 l0 = __float2bfloat16(v0 - __bfloat162float(h0));
                    __nv_bfloat16 l1 = __float2bfloat16(v1 - __bfloat162float(h1));
                    __nv_bfloat162 ph{h0, h1}, pl{l0, l1};
                    size_t gi = (size_t)gr * N + gc;
                    *reinterpret_cast<__nv_bfloat162*>(outHi + gi) = ph;
                    *reinterpret_cast<__nv_bfloat162*>(outLo + gi) = pl;
                }
            } else {
#pragma unroll
                for (int hrow = 0; hrow < 2; hrow++) {
                    int gr = gr0 + hrow * 8;
                    float2 v{d[hrow * 2], d[hrow * 2 + 1]};
                    *reinterpret_cast<float2*>(outF + (size_t)gr * N + gc) = v;
                }
            }
        }
    }
}

// =============================== launch ===============================
extern "C" void kernel_launch(void* const* d_in, const int* in_sizes, int n_in,
                              void* d_out, int out_size)
{
    (void)in_sizes; (void)n_in; (void)out_size;
    const float* x     = (const float*)d_in[0];
    const int*   eids  = (const int*)d_in[1];
    const float* wi    = (const float*)d_in[2];
    const float* wo    = (const float*)d_in[3];
    const float* cwi_a = (const float*)d_in[4];
    const float* cwi_b = (const float*)d_in[5];
    const float* cwo_a = (const float*)d_in[6];
    const float* cwo_b = (const float*)d_in[7];
    const float* ewi_a = (const float*)d_in[8];
    const float* ewi_b = (const float*)d_in[9];
    const float* ewo_a = (const float*)d_in[10];
    const float* ewo_b = (const float*)d_in[11];
    float* out = (float*)d_out;

    __nv_bfloat16 *hhi, *hlo;
    float *U1, *U2;
    cudaGetSymbolAddress((void**)&hhi, g_hid_hi);
    cudaGetSymbolAddress((void**)&hlo, g_hid_lo);
    cudaGetSymbolAddress((void**)&U1, g_U1);
    cudaGetSymbolAddress((void**)&U2, g_U2);

    cudaFuncSetAttribute(gemm_mma<1>, cudaFuncAttributeMaxDynamicSharedMemorySize, SMEM_DYN);
    cudaFuncSetAttribute(gemm_mma<0>, cudaFuncAttributeMaxDynamicSharedMemorySize, SMEM_DYN);

    lora_proj<0><<<T_TOK / 8, 256>>>(x, nullptr, nullptr, cwi_a, ewi_a, eids, U1, D_DIM);

    dim3 g1(F_DIM / 128, T_TOK / 128);
    gemm_mma<1><<<g1, 256, SMEM_DYN>>>(x, nullptr, nullptr, wi, U1, cwi_b, ewi_b, eids,
                                       nullptr, hhi, hlo, F_DIM, D_DIM);

    lora_proj<1><<<T_TOK / 8, 256>>>(nullptr, hhi, hlo, cwo_a, ewo_a, eids, U2, F_DIM);

    dim3 g2(D_DIM / 128, T_TOK / 128);
    gemm_mma<0><<<g2, 256, SMEM_DYN>>>(nullptr, hhi, hlo, wo, U2, cwo_b, ewo_b, eids,
                                       out, nullptr, nullptr, D_DIM, F_DIM);
}

// round 8
// speedup vs baseline: 1.7595x; 1.0684x over previous
#include <cuda_runtime.h>
#include <cuda_bf16.h>
#include <cstdint>
#include <cstddef>

#define T_TOK 16384
#define D_DIM 1024
#define F_DIM 4096
#define E_EXP 8
#define ALPHA_F 2.0f

// ---- device scratch (allocation-free) ----
__device__ __nv_bfloat16 g_hid_hi[(size_t)T_TOK * F_DIM];
__device__ __nv_bfloat16 g_hid_lo[(size_t)T_TOK * F_DIM];
__device__ __nv_bfloat16 g_x_hi[(size_t)T_TOK * D_DIM];
__device__ __nv_bfloat16 g_x_lo[(size_t)T_TOK * D_DIM];
__device__ __nv_bfloat16 g_wi_hi[(size_t)F_DIM * D_DIM];
__device__ __nv_bfloat16 g_wi_lo[(size_t)F_DIM * D_DIM];
__device__ __nv_bfloat16 g_wo_hi[(size_t)D_DIM * F_DIM];
__device__ __nv_bfloat16 g_wo_lo[(size_t)D_DIM * F_DIM];
__device__ float g_U1[T_TOK * 32];
__device__ float g_U2[T_TOK * 32];
__device__ __nv_bfloat16 g_U1_hi[T_TOK * 32], g_U1_lo[T_TOK * 32];
__device__ __nv_bfloat16 g_U2_hi[T_TOK * 32], g_U2_lo[T_TOK * 32];
__device__ __nv_bfloat16 g_wbc1_hi[F_DIM * 16], g_wbc1_lo[F_DIM * 16];
__device__ __nv_bfloat16 g_wbe1_hi[E_EXP * F_DIM * 16], g_wbe1_lo[E_EXP * F_DIM * 16];
__device__ __nv_bfloat16 g_wbc2_hi[D_DIM * 16], g_wbc2_lo[D_DIM * 16];
__device__ __nv_bfloat16 g_wbe2_hi[E_EXP * D_DIM * 16], g_wbe2_lo[E_EXP * D_DIM * 16];

// ---------------- helpers ----------------
__device__ __forceinline__ uint32_t smem_u32(const void* p) {
    uint32_t a;
    asm("{ .reg .u64 t; cvta.to.shared.u64 t, %1; cvt.u32.u64 %0, t; }" : "=r"(a) : "l"(p));
    return a;
}
__device__ __forceinline__ void ldsm_x4(uint32_t* r, uint32_t addr) {
    asm volatile("ldmatrix.sync.aligned.m8n8.x4.shared.b16 {%0,%1,%2,%3}, [%4];"
                 : "=r"(r[0]), "=r"(r[1]), "=r"(r[2]), "=r"(r[3]) : "r"(addr));
}
__device__ __forceinline__ void ldsm_x2(uint32_t* r, uint32_t addr) {
    asm volatile("ldmatrix.sync.aligned.m8n8.x2.shared.b16 {%0,%1}, [%2];"
                 : "=r"(r[0]), "=r"(r[1]) : "r"(addr));
}
__device__ __forceinline__ void mma_bf16(float* d, const uint32_t* a, const uint32_t* b) {
    asm volatile(
        "mma.sync.aligned.m16n8k16.row.col.f32.bf16.bf16.f32 "
        "{%0,%1,%2,%3},{%4,%5,%6,%7},{%8,%9},{%0,%1,%2,%3};"
        : "+f"(d[0]), "+f"(d[1]), "+f"(d[2]), "+f"(d[3])
        : "r"(a[0]), "r"(a[1]), "r"(a[2]), "r"(a[3]), "r"(b[0]), "r"(b[1]));
}
__device__ __forceinline__ void cpa16(uint32_t dst, const void* src) {
    asm volatile("cp.async.cg.shared.global [%0], [%1], 16;" :: "r"(dst), "l"(src));
}
__device__ __forceinline__ void cpa_commit() {
    asm volatile("cp.async.commit_group;" ::: "memory");
}
template <int NW>
__device__ __forceinline__ void cpa_wait() {
    asm volatile("cp.async.wait_group %0;" :: "n"(NW) : "memory");
}

// ================ pre-pass: split fp32 -> bf16 hi/lo ================
__global__ __launch_bounds__(256) void split_kernel(
    const float* __restrict__ src, __nv_bfloat16* __restrict__ hi,
    __nv_bfloat16* __restrict__ lo, int n)
{
    int i = (blockIdx.x * 256 + threadIdx.x) * 8;
    if (i >= n) return;
    float a[8];
    *(float4*)&a[0] = *(const float4*)(src + i);
    *(float4*)&a[4] = *(const float4*)(src + i + 4);
    uint32_t hw[4], lw[4];
#pragma unroll
    for (int j = 0; j < 4; j++) {
        float x0 = a[2 * j], x1 = a[2 * j + 1];
        __nv_bfloat16 h0 = __float2bfloat16(x0), h1 = __float2bfloat16(x1);
        __nv_bfloat16 l0 = __float2bfloat16(x0 - __bfloat162float(h0));
        __nv_bfloat16 l1 = __float2bfloat16(x1 - __bfloat162float(h1));
        __nv_bfloat162 ph{h0, h1}, pl{l0, l1};
        hw[j] = *reinterpret_cast<uint32_t*>(&ph);
        lw[j] = *reinterpret_cast<uint32_t*>(&pl);
    }
    *(uint4*)(hi + i) = make_uint4(hw[0], hw[1], hw[2], hw[3]);
    *(uint4*)(lo + i) = make_uint4(lw[0], lw[1], lw[2], lw[3]);
}

// ================= low-rank projection (U = ALPHA * X . Wa^T) =================
template <int BF>
__global__ __launch_bounds__(256) void lora_proj(
    const float* __restrict__ Xf, const __nv_bfloat16* __restrict__ Xhi,
    const __nv_bfloat16* __restrict__ Xlo,
    const float* __restrict__ Wa_c, const float* __restrict__ Wa_e,
    const int* __restrict__ eids, float* __restrict__ U, int K)
{
    __shared__ float xs[8][1024];
    const int tid = threadIdx.x, t0 = blockIdx.x * 8;
    const int e = eids[t0 >> 9];
    const int r = tid >> 3, sub = tid & 7;
    const float* wrow = (r < 16) ? (Wa_c + (size_t)r * K)
                                 : (Wa_e + ((size_t)e * 16 + (r - 16)) * (size_t)K);
    float acc[8];
#pragma unroll
    for (int t = 0; t < 8; t++) acc[t] = 0.f;

    for (int kc = 0; kc < K; kc += 1024) {
        __syncthreads();
        if (BF) {
#pragma unroll
            for (int i = 0; i < 4; i++) {
                int f = tid + i * 256, tt = f >> 7, c8 = f & 127;
                size_t g = (size_t)(t0 + tt) * K + kc + c8 * 8;
                uint4 h = *(const uint4*)(Xhi + g), l = *(const uint4*)(Xlo + g);
                const uint32_t* hw = (const uint32_t*)&h;
                const uint32_t* lw = (const uint32_t*)&l;
#pragma unroll
                for (int w = 0; w < 4; w++) {
                    float2 fh = __bfloat1622float2(*(const __nv_bfloat162*)&hw[w]);
                    float2 fl = __bfloat1622float2(*(const __nv_bfloat162*)&lw[w]);
                    xs[tt][c8 * 8 + w * 2] = fh.x + fl.x;
                    xs[tt][c8 * 8 + w * 2 + 1] = fh.y + fl.y;
                }
            }
        } else {
#pragma unroll
            for (int i = 0; i < 8; i++) {
                int f = tid + i * 256, tt = f >> 8, c4 = f & 255;
                *(float4*)&xs[tt][c4 * 4] =
                    *(const float4*)(Xf + (size_t)(t0 + tt) * K + kc + c4 * 4);
            }
        }
        __syncthreads();
        const float4* w4 = (const float4*)(wrow + kc);
#pragma unroll 4
        for (int i = 0; i < 32; i++) {
            int f = i * 8 + sub;
            float4 w = w4[f];
#pragma unroll
            for (int t = 0; t < 8; t++) {
                float4 xv = *(const float4*)&xs[t][f * 4];
                acc[t] += w.x * xv.x + w.y * xv.y + w.z * xv.z + w.w * xv.w;
            }
        }
    }
#pragma unroll
    for (int off = 4; off > 0; off >>= 1)
#pragma unroll
        for (int t = 0; t < 8; t++) acc[t] += __shfl_down_sync(0xffffffffu, acc[t], off, 8);
    if (sub == 0)
#pragma unroll
        for (int t = 0; t < 8; t++) U[(size_t)(t0 + t) * 32 + r] = ALPHA_F * acc[t];
}

// ================== cp.async split-bf16 GEMM + fused LoRA ==================
// CTA tile 256x128, BK=64, 8 warps @ 64x64. All operands pre-split bf16 hi/lo.
// smem stage: Ahi 32K | Alo 32K | Bhi 16K | Blo 16K = 96KB; 2 stages.
#define STG_A 65536
#define STG 98304
#define SMEM_DYN (2 * STG + 1024)

template <int MODE>  // 1: relu -> bf16 hi/lo out; 0: fp32 out
__global__ __launch_bounds__(256, 1) void gemm_cp(
    const __nv_bfloat16* __restrict__ Ahi, const __nv_bfloat16* __restrict__ Alo,
    const __nv_bfloat16* __restrict__ Bhi, const __nv_bfloat16* __restrict__ Blo,
    const __nv_bfloat16* __restrict__ Uhi, const __nv_bfloat16* __restrict__ Ulo,
    const __nv_bfloat16* __restrict__ Wbc_hi, const __nv_bfloat16* __restrict__ Wbc_lo,
    const __nv_bfloat16* __restrict__ Wbe_hi, const __nv_bfloat16* __restrict__ Wbe_lo,
    const int* __restrict__ eids,
    float* __restrict__ outF, __nv_bfloat16* __restrict__ outHi,
    __nv_bfloat16* __restrict__ outLo, int N, int K)
{
    extern __shared__ char smraw[];
    uint32_t sd0 = smem_u32(smraw);
    char* smem = smraw + (((sd0 + 1023u) & ~1023u) - sd0);
    const uint32_t Sb = smem_u32(smem);

    const int tid = threadIdx.x, wid = tid >> 5, lane = tid & 31;
    const int m0 = blockIdx.y * 256, n0 = blockIdx.x * 128;
    const int e = eids[m0 >> 9];

    const int m_w = (wid >> 1) * 64, n_w = (wid & 1) * 64;
    const int arow = lane & 15, ac8 = (lane >> 4) * 16;
    const int brow = lane & 7, bc8 = ((lane >> 3) & 1) * 16;

    float acc[4][8][4];
#pragma unroll
    for (int i = 0; i < 4; i++)
#pragma unroll
        for (int j = 0; j < 8; j++)
#pragma unroll
            for (int q = 0; q < 4; q++) acc[i][j][q] = 0.f;

    const int KCH = K >> 6, NCH = KCH + 1;

    // ---- async load of chunk ch into stage s ----
    auto load_stage = [&](int ch, int s) {
        const uint32_t Ab = Sb + s * STG;
        const uint32_t Bb = Ab + STG_A;
        if (ch < KCH) {
            const int kc = ch << 6;
            {   // A: thread = one row (256 rows), 8 hi + 8 lo chunks
                const int row = tid;
                const __nv_bfloat16* sh = Ahi + (size_t)(m0 + row) * K + kc;
                const __nv_bfloat16* sl = Alo + (size_t)(m0 + row) * K + kc;
                const uint32_t ro = (uint32_t)row * 128, xm = (uint32_t)(row & 7) << 4;
#pragma unroll
                for (int j = 0; j < 8; j++) {
                    uint32_t d = ro + ((uint32_t)(j * 16) ^ xm);
                    cpa16(Ab + d, sh + j * 8);
                    cpa16(Ab + 32768 + d, sl + j * 8);
                }
            }
            {   // B: thread -> (row = tid>>1, half = tid&1), 4 hi + 4 lo
                const int row = tid >> 1, hf = tid & 1;
                const __nv_bfloat16* sh = Bhi + (size_t)(n0 + row) * K + kc + hf * 32;
                const __nv_bfloat16* sl = Blo + (size_t)(n0 + row) * K + kc + hf * 32;
                const uint32_t ro = (uint32_t)row * 128, xm = (uint32_t)(row & 7) << 4;
#pragma unroll
                for (int j = 0; j < 4; j++) {
                    uint32_t d = ro + ((uint32_t)(hf * 64 + j * 16) ^ xm);
                    cpa16(Bb + d, sh + j * 8);
                    cpa16(Bb + 16384 + d, sl + j * 8);
                }
            }
        } else {
            {   // A-lora: U rows, 32 bf16 = 4 chunks each array
                const int row = tid;
                const __nv_bfloat16* sh = Uhi + (size_t)(m0 + row) * 32;
                const __nv_bfloat16* sl = Ulo + (size_t)(m0 + row) * 32;
                const uint32_t ro = (uint32_t)row * 128, xm = (uint32_t)(row & 7) << 4;
#pragma unroll
                for (int j = 0; j < 4; j++) {
                    uint32_t d = ro + ((uint32_t)(j * 16) ^ xm);
                    cpa16(Ab + d, sh + j * 8);
                    cpa16(Ab + 32768 + d, sl + j * 8);
                }
            }
            if (tid < 128) {  // B-lora: k 0:16 = Wbc, 16:32 = Wbe[e]
                const int row = tid;
                const uint32_t ro = (uint32_t)row * 128, xm = (uint32_t)(row & 7) << 4;
                const __nv_bfloat16* ch_ = Wbc_hi + (size_t)(n0 + row) * 16;
                const __nv_bfloat16* cl_ = Wbc_lo + (size_t)(n0 + row) * 16;
                const __nv_bfloat16* eh_ = Wbe_hi + (size_t)e * N * 16 + (size_t)(n0 + row) * 16;
                const __nv_bfloat16* el_ = Wbe_lo + (size_t)e * N * 16 + (size_t)(n0 + row) * 16;
#pragma unroll
                for (int j = 0; j < 2; j++) {
                    uint32_t d0 = ro + ((uint32_t)(j * 16) ^ xm);
                    uint32_t d1 = ro + ((uint32_t)(32 + j * 16) ^ xm);
                    cpa16(Bb + d0, ch_ + j * 8);
                    cpa16(Bb + 16384 + d0, cl_ + j * 8);
                    cpa16(Bb + d1, eh_ + j * 8);
                    cpa16(Bb + 16384 + d1, el_ + j * 8);
                }
            }
        }
    };

    // ---- MMA over stage s ----
    auto compute_stage = [&](int s, int nks) {
        const uint32_t Ab = Sb + s * STG;
        const uint32_t Bb = Ab + STG_A;
#pragma unroll
        for (int ks = 0; ks < 4; ks++) {
            if (ks >= nks) break;
            const int kb = ks * 32;
            uint32_t ahi[4][4], alo[4][4];
#pragma unroll
            for (int mi = 0; mi < 4; mi++) {
                int row = m_w + mi * 16 + arow;
                uint32_t addr = Ab + (uint32_t)row * 128 +
                                ((uint32_t)(kb + ac8) ^ ((uint32_t)(row & 7) << 4));
                ldsm_x4(ahi[mi], addr);
                ldsm_x4(alo[mi], addr + 32768);
            }
#pragma unroll
            for (int ni = 0; ni < 8; ni++) {
                int row = n_w + ni * 8 + brow;
                uint32_t addr = Bb + (uint32_t)row * 128 +
                                ((uint32_t)(kb + bc8) ^ ((uint32_t)(row & 7) << 4));
                uint32_t bh[2], bl[2];
                ldsm_x2(bh, addr);
                ldsm_x2(bl, addr + 16384);
#pragma unroll
                for (int mi = 0; mi < 4; mi++) {
                    mma_bf16(acc[mi][ni], ahi[mi], bh);
                    mma_bf16(acc[mi][ni], ahi[mi], bl);
                    mma_bf16(acc[mi][ni], alo[mi], bh);
                }
            }
        }
    };

    // ---- pipelined mainloop (2-stage cp.async) ----
    load_stage(0, 0);
    cpa_commit();
    for (int ch = 0; ch < NCH; ch++) {
        if (ch + 1 < NCH) {
            load_stage(ch + 1, (ch + 1) & 1);
            cpa_commit();
            cpa_wait<1>();
        } else {
            cpa_wait<0>();
        }
        __syncthreads();
        compute_stage(ch & 1, (ch < KCH) ? 4 : 2);
        __syncthreads();
    }

    // ---- epilogue ----
    const int er = lane >> 2, ec = (lane & 3) * 2;
#pragma unroll
    for (int mi = 0; mi < 4; mi++) {
#pragma unroll
        for (int ni = 0; ni < 8; ni++) {
            float* d = acc[mi][ni];
            int gr0 = m0 + m_w + mi * 16 + er;
            int gc = n0 + n_w + ni * 8 + ec;
#pragma unroll
            for (int hrow = 0; hrow < 2; hrow++) {
                int gr = gr0 + hrow * 8;
                if (MODE == 1) {
                    float v0 = fmaxf(d[hrow * 2], 0.f), v1 = fmaxf(d[hrow * 2 + 1], 0.f);
                    __nv_bfloat16 h0 = __float2bfloat16(v0), h1 = __float2bfloat16(v1);
                    __nv_bfloat16 l0 = __float2bfloat16(v0 - __bfloat162float(h0));
                    __nv_bfloat16 l1 = __float2bfloat16(v1 - __bfloat162float(h1));
                    __nv_bfloat162 ph{h0, h1}, pl{l0, l1};
                    size_t gi = (size_t)gr * N + gc;
                    *reinterpret_cast<__nv_bfloat162*>(outHi + gi) = ph;
                    *reinterpret_cast<__nv_bfloat162*>(outLo + gi) = pl;
                } else {
                    float2 v{d[hrow * 2], d[hrow * 2 + 1]};
                    *reinterpret_cast<float2*>(outF + (size_t)gr * N + gc) = v;
                }
            }
        }
    }
}

// =============================== launch ===============================
static inline void split_launch(const float* s, __nv_bfloat16* h, __nv_bfloat16* l, int n) {
    split_kernel<<<(n / 8 + 255) / 256, 256>>>(s, h, l, n);
}

extern "C" void kernel_launch(void* const* d_in, const int* in_sizes, int n_in,
                              void* d_out, int out_size)
{
    (void)in_sizes; (void)n_in; (void)out_size;
    const float* x     = (const float*)d_in[0];
    const int*   eids  = (const int*)d_in[1];
    const float* wi    = (const float*)d_in[2];
    const float* wo    = (const float*)d_in[3];
    const float* cwi_a = (const float*)d_in[4];
    const float* cwi_b = (const float*)d_in[5];
    const float* cwo_a = (const float*)d_in[6];
    const float* cwo_b = (const float*)d_in[7];
    const float* ewi_a = (const float*)d_in[8];
    const float* ewi_b = (const float*)d_in[9];
    const float* ewo_a = (const float*)d_in[10];
    const float* ewo_b = (const float*)d_in[11];
    float* out = (float*)d_out;

    __nv_bfloat16 *hhi, *hlo, *xhi, *xlo, *wihi, *wilo, *wohi, *wolo;
    __nv_bfloat16 *u1hi, *u1lo, *u2hi, *u2lo;
    __nv_bfloat16 *wbc1h, *wbc1l, *wbe1h, *wbe1l, *wbc2h, *wbc2l, *wbe2h, *wbe2l;
    float *U1, *U2;
    cudaGetSymbolAddress((void**)&hhi, g_hid_hi);  cudaGetSymbolAddress((void**)&hlo, g_hid_lo);
    cudaGetSymbolAddress((void**)&xhi, g_x_hi);    cudaGetSymbolAddress((void**)&xlo, g_x_lo);
    cudaGetSymbolAddress((void**)&wihi, g_wi_hi);  cudaGetSymbolAddress((void**)&wilo, g_wi_lo);
    cudaGetSymbolAddress((void**)&wohi, g_wo_hi);  cudaGetSymbolAddress((void**)&wolo, g_wo_lo);
    cudaGetSymbolAddress((void**)&U1, g_U1);       cudaGetSymbolAddress((void**)&U2, g_U2);
    cudaGetSymbolAddress((void**)&u1hi, g_U1_hi);  cudaGetSymbolAddress((void**)&u1lo, g_U1_lo);
    cudaGetSymbolAddress((void**)&u2hi, g_U2_hi);  cudaGetSymbolAddress((void**)&u2lo, g_U2_lo);
    cudaGetSymbolAddress((void**)&wbc1h, g_wbc1_hi); cudaGetSymbolAddress((void**)&wbc1l, g_wbc1_lo);
    cudaGetSymbolAddress((void**)&wbe1h, g_wbe1_hi); cudaGetSymbolAddress((void**)&wbe1l, g_wbe1_lo);
    cudaGetSymbolAddress((void**)&wbc2h, g_wbc2_hi); cudaGetSymbolAddress((void**)&wbc2l, g_wbc2_lo);
    cudaGetSymbolAddress((void**)&wbe2h, g_wbe2_hi); cudaGetSymbolAddress((void**)&wbe2l, g_wbe2_lo);

    cudaFuncSetAttribute(gemm_cp<1>, cudaFuncAttributeMaxDynamicSharedMemorySize, SMEM_DYN);
    cudaFuncSetAttribute(gemm_cp<0>, cudaFuncAttributeMaxDynamicSharedMemorySize, SMEM_DYN);

    // pre-splits
    split_launch(x, xhi, xlo, T_TOK * D_DIM);
    split_launch(wi, wihi, wilo, F_DIM * D_DIM);
    split_launch(wo, wohi, wolo, D_DIM * F_DIM);
    split_launch(cwi_b, wbc1h, wbc1l, F_DIM * 16);
    split_launch(ewi_b, wbe1h, wbe1l, E_EXP * F_DIM * 16);
    split_launch(cwo_b, wbc2h, wbc2l, D_DIM * 16);
    split_launch(ewo_b, wbe2h, wbe2l, E_EXP * D_DIM * 16);

    // stage 1
    lora_proj<0><<<T_TOK / 8, 256>>>(x, nullptr, nullptr, cwi_a, ewi_a, eids, U1, D_DIM);
    split_launch(U1, u1hi, u1lo, T_TOK * 32);
    dim3 g1(F_DIM / 128, T_TOK / 256);
    gemm_cp<1><<<g1, 256, SMEM_DYN>>>(xhi, xlo, wihi, wilo, u1hi, u1lo,
                                      wbc1h, wbc1l, wbe1h, wbe1l, eids,
                                      nullptr, hhi, hlo, F_DIM, D_DIM);

    // stage 2
    lora_proj<1><<<T_TOK / 8, 256>>>(nullptr, hhi, hlo, cwo_a, ewo_a, eids, U2, F_DIM);
    split_launch(U2, u2hi, u2lo, T_TOK * 32);
    dim3 g2(D_DIM / 128, T_TOK / 256);
    gemm_cp<0><<<g2, 256, SMEM_DYN>>>(hhi, hlo, wohi, wolo, u2hi, u2lo,
                                      wbc2h, wbc2l, wbe2h, wbe2l, eids,
                                      out, nullptr, nullptr, D_DIM, F_DIM);
}

// round 9
// speedup vs baseline: 2.2216x; 1.2626x over previous
#include <cuda_runtime.h>
#include <cuda_fp16.h>
#include <cstdint>
#include <cstddef>

#define T_TOK 16384
#define D_DIM 1024
#define F_DIM 4096
#define E_EXP 8
#define ALPHA_F 2.0f

// ---- device scratch (allocation-free) ----
__device__ __half g_hid_hi[(size_t)T_TOK * F_DIM];
__device__ __half g_hid_lo[(size_t)T_TOK * F_DIM];
__device__ __half g_x_hi[(size_t)T_TOK * D_DIM];
__device__ __half g_x_lo[(size_t)T_TOK * D_DIM];
__device__ __half g_wi_hi[(size_t)F_DIM * D_DIM];   // weights: hi only
__device__ __half g_wo_hi[(size_t)D_DIM * F_DIM];
__device__ float g_U1[T_TOK * 32];
__device__ float g_U2[T_TOK * 32];
__device__ __half g_U1_hi[T_TOK * 32], g_U1_lo[T_TOK * 32];
__device__ __half g_U2_hi[T_TOK * 32], g_U2_lo[T_TOK * 32];
__device__ __half g_wbc1_hi[F_DIM * 16];
__device__ __half g_wbe1_hi[E_EXP * F_DIM * 16];
__device__ __half g_wbc2_hi[D_DIM * 16];
__device__ __half g_wbe2_hi[E_EXP * D_DIM * 16];

// ---------------- helpers ----------------
__device__ __forceinline__ uint32_t smem_u32(const void* p) {
    uint32_t a;
    asm("{ .reg .u64 t; cvta.to.shared.u64 t, %1; cvt.u32.u64 %0, t; }" : "=r"(a) : "l"(p));
    return a;
}
__device__ __forceinline__ void ldsm_x4(uint32_t* r, uint32_t addr) {
    asm volatile("ldmatrix.sync.aligned.m8n8.x4.shared.b16 {%0,%1,%2,%3}, [%4];"
                 : "=r"(r[0]), "=r"(r[1]), "=r"(r[2]), "=r"(r[3]) : "r"(addr));
}
__device__ __forceinline__ void mma_f16(float* d, const uint32_t* a, const uint32_t* b) {
    asm volatile(
        "mma.sync.aligned.m16n8k16.row.col.f32.f16.f16.f32 "
        "{%0,%1,%2,%3},{%4,%5,%6,%7},{%8,%9},{%0,%1,%2,%3};"
        : "+f"(d[0]), "+f"(d[1]), "+f"(d[2]), "+f"(d[3])
        : "r"(a[0]), "r"(a[1]), "r"(a[2]), "r"(a[3]), "r"(b[0]), "r"(b[1]));
}
__device__ __forceinline__ void cpa16(uint32_t dst, const void* src) {
    asm volatile("cp.async.cg.shared.global [%0], [%1], 16;" :: "r"(dst), "l"(src));
}
__device__ __forceinline__ void cpa_commit() {
    asm volatile("cp.async.commit_group;" ::: "memory");
}
template <int NW>
__device__ __forceinline__ void cpa_wait() {
    asm volatile("cp.async.wait_group %0;" :: "n"(NW) : "memory");
}

// ================ pre-pass: split fp32 -> fp16 hi(+lo) ================
__global__ __launch_bounds__(256) void split_full(
    const float* __restrict__ src, __half* __restrict__ hi,
    __half* __restrict__ lo, int n)
{
    int i = (blockIdx.x * 256 + threadIdx.x) * 8;
    if (i >= n) return;
    float a[8];
    *(float4*)&a[0] = *(const float4*)(src + i);
    *(float4*)&a[4] = *(const float4*)(src + i + 4);
    uint32_t hw[4], lw[4];
#pragma unroll
    for (int j = 0; j < 4; j++) {
        float x0 = a[2 * j], x1 = a[2 * j + 1];
        __half h0 = __float2half_rn(x0), h1 = __float2half_rn(x1);
        __half l0 = __float2half_rn(x0 - __half2float(h0));
        __half l1 = __float2half_rn(x1 - __half2float(h1));
        __half2 ph{h0, h1}, pl{l0, l1};
        hw[j] = *reinterpret_cast<uint32_t*>(&ph);
        lw[j] = *reinterpret_cast<uint32_t*>(&pl);
    }
    *(uint4*)(hi + i) = make_uint4(hw[0], hw[1], hw[2], hw[3]);
    *(uint4*)(lo + i) = make_uint4(lw[0], lw[1], lw[2], lw[3]);
}

__global__ __launch_bounds__(256) void split_hi(
    const float* __restrict__ src, __half* __restrict__ hi, int n)
{
    int i = (blockIdx.x * 256 + threadIdx.x) * 8;
    if (i >= n) return;
    float a[8];
    *(float4*)&a[0] = *(const float4*)(src + i);
    *(float4*)&a[4] = *(const float4*)(src + i + 4);
    uint32_t hw[4];
#pragma unroll
    for (int j = 0; j < 4; j++) {
        __half2 ph{__float2half_rn(a[2 * j]), __float2half_rn(a[2 * j + 1])};
        hw[j] = *reinterpret_cast<uint32_t*>(&ph);
    }
    *(uint4*)(hi + i) = make_uint4(hw[0], hw[1], hw[2], hw[3]);
}

// ================= low-rank projection (U = ALPHA * X . Wa^T) =================
// BF=0: X fp32.  BF=1: X fp16 (hi array only; lo negligible for rank-16 term).
template <int BF>
__global__ __launch_bounds__(256) void lora_proj(
    const float* __restrict__ Xf, const __half* __restrict__ Xhi,
    const float* __restrict__ Wa_c, const float* __restrict__ Wa_e,
    const int* __restrict__ eids, float* __restrict__ U, int K)
{
    __shared__ float xs[8][1024];
    const int tid = threadIdx.x, t0 = blockIdx.x * 8;
    const int e = eids[t0 >> 9];
    const int r = tid >> 3, sub = tid & 7;
    const float* wrow = (r < 16) ? (Wa_c + (size_t)r * K)
                                 : (Wa_e + ((size_t)e * 16 + (r - 16)) * (size_t)K);
    float acc[8];
#pragma unroll
    for (int t = 0; t < 8; t++) acc[t] = 0.f;

    for (int kc = 0; kc < K; kc += 1024) {
        __syncthreads();
        if (BF) {
#pragma unroll
            for (int i = 0; i < 4; i++) {
                int f = tid + i * 256, tt = f >> 7, c8 = f & 127;
                size_t g = (size_t)(t0 + tt) * K + kc + c8 * 8;
                uint4 h = *(const uint4*)(Xhi + g);
                const uint32_t* hw = (const uint32_t*)&h;
#pragma unroll
                for (int w = 0; w < 4; w++) {
                    float2 fh = __half22float2(*(const __half2*)&hw[w]);
                    xs[tt][c8 * 8 + w * 2] = fh.x;
                    xs[tt][c8 * 8 + w * 2 + 1] = fh.y;
                }
            }
        } else {
#pragma unroll
            for (int i = 0; i < 8; i++) {
                int f = tid + i * 256, tt = f >> 8, c4 = f & 255;
                *(float4*)&xs[tt][c4 * 4] =
                    *(const float4*)(Xf + (size_t)(t0 + tt) * K + kc + c4 * 4);
            }
        }
        __syncthreads();
        const float4* w4 = (const float4*)(wrow + kc);
#pragma unroll 4
        for (int i = 0; i < 32; i++) {
            int f = i * 8 + sub;
            float4 w = w4[f];
#pragma unroll
            for (int t = 0; t < 8; t++) {
                float4 xv = *(const float4*)&xs[t][f * 4];
                acc[t] += w.x * xv.x + w.y * xv.y + w.z * xv.z + w.w * xv.w;
            }
        }
    }
#pragma unroll
    for (int off = 4; off > 0; off >>= 1)
#pragma unroll
        for (int t = 0; t < 8; t++) acc[t] += __shfl_down_sync(0xffffffffu, acc[t], off, 8);
    if (sub == 0)
#pragma unroll
        for (int t = 0; t < 8; t++) U[(size_t)(t0 + t) * 32 + r] = ALPHA_F * acc[t];
}

// ============= fp16 2-product GEMM + fused LoRA (cp.async pipeline) =============
// C = (Ahi + Alo) . Bhi^T  (dropped A.Blo term ~2^-12).
// CTA 256x128, BK=64, 8 warps @ 64x64.
// smem stage: Ahi 32K | Alo 32K | Bhi 16K = 80KB; 2 stages = 160KB.
#define STG_AHI 0
#define STG_ALO 32768
#define STG_BHI 65536
#define STG 81920
#define SMEM_DYN (2 * STG + 1024)

template <int MODE>  // 1: relu -> fp16 hi/lo out; 0: fp32 out
__global__ __launch_bounds__(256, 1) void gemm_cp(
    const __half* __restrict__ Ahi, const __half* __restrict__ Alo,
    const __half* __restrict__ Bhi,
    const __half* __restrict__ Uhi, const __half* __restrict__ Ulo,
    const __half* __restrict__ Wbc_hi, const __half* __restrict__ Wbe_hi,
    const int* __restrict__ eids,
    float* __restrict__ outF, __half* __restrict__ outHi,
    __half* __restrict__ outLo, int N, int K)
{
    extern __shared__ char smraw[];
    uint32_t sd0 = smem_u32(smraw);
    char* smem = smraw + (((sd0 + 1023u) & ~1023u) - sd0);
    const uint32_t Sb = smem_u32(smem);

    const int tid = threadIdx.x, wid = tid >> 5, lane = tid & 31;
    const int m0 = blockIdx.y * 256, n0 = blockIdx.x * 128;
    const int e = eids[m0 >> 9];

    const int m_w = (wid >> 1) * 64, n_w = (wid & 1) * 64;
    const int arow = lane & 15, ac8 = (lane >> 4) * 16;
    // B x4 pairing: lanes 0-7 -> (ntile 2p, k-lo), 8-15 -> (2p, k-hi),
    //               16-23 -> (2p+1, k-lo), 24-31 -> (2p+1, k-hi)
    const int brow_base = ((lane >> 4) & 1) * 8 + (lane & 7);
    const int bk8 = ((lane >> 3) & 1) * 16;

    float acc[4][8][4];
#pragma unroll
    for (int i = 0; i < 4; i++)
#pragma unroll
        for (int j = 0; j < 8; j++)
#pragma unroll
            for (int q = 0; q < 4; q++) acc[i][j][q] = 0.f;

    const int KCH = K >> 6, NCH = KCH + 1;

    // ---- async load of chunk ch into stage s ----
    auto load_stage = [&](int ch, int s) {
        const uint32_t Ab = Sb + s * STG;
        if (ch < KCH) {
            const int kc = ch << 6;
            {   // A: thread = one row (256 rows), 128B hi + 128B lo
                const int row = tid;
                const __half* sh = Ahi + (size_t)(m0 + row) * K + kc;
                const __half* sl = Alo + (size_t)(m0 + row) * K + kc;
                const uint32_t ro = (uint32_t)row * 128, xm = (uint32_t)(row & 7) << 4;
#pragma unroll
                for (int j = 0; j < 8; j++) {
                    uint32_t d = ro + ((uint32_t)(j * 16) ^ xm);
                    cpa16(Ab + STG_AHI + d, sh + j * 8);
                    cpa16(Ab + STG_ALO + d, sl + j * 8);
                }
            }
            {   // B hi: row = tid>>1, half = tid&1 (64B each)
                const int row = tid >> 1, hf = tid & 1;
                const __half* sh = Bhi + (size_t)(n0 + row) * K + kc + hf * 32;
                const uint32_t ro = (uint32_t)row * 128, xm = (uint32_t)(row & 7) << 4;
#pragma unroll
                for (int j = 0; j < 4; j++) {
                    uint32_t d = ro + ((uint32_t)(hf * 64 + j * 16) ^ xm);
                    cpa16(Ab + STG_BHI + d, sh + j * 8);
                }
            }
        } else {
            {   // A-lora: U hi/lo rows (32 fp16 = 64B)
                const int row = tid;
                const __half* sh = Uhi + (size_t)(m0 + row) * 32;
                const __half* sl = Ulo + (size_t)(m0 + row) * 32;
                const uint32_t ro = (uint32_t)row * 128, xm = (uint32_t)(row & 7) << 4;
#pragma unroll
                for (int j = 0; j < 4; j++) {
                    uint32_t d = ro + ((uint32_t)(j * 16) ^ xm);
                    cpa16(Ab + STG_AHI + d, sh + j * 8);
                    cpa16(Ab + STG_ALO + d, sl + j * 8);
                }
            }
            if (tid < 128) {  // B-lora hi: k 0:16 = Wbc, 16:32 = Wbe[e]
                const int row = tid;
                const uint32_t ro = (uint32_t)row * 128, xm = (uint32_t)(row & 7) << 4;
                const __half* ch_ = Wbc_hi + (size_t)(n0 + row) * 16;
                const __half* eh_ = Wbe_hi + (size_t)e * N * 16 + (size_t)(n0 + row) * 16;
#pragma unroll
                for (int j = 0; j < 2; j++) {
                    uint32_t d0 = ro + ((uint32_t)(j * 16) ^ xm);
                    uint32_t d1 = ro + ((uint32_t)(32 + j * 16) ^ xm);
                    cpa16(Ab + STG_BHI + d0, ch_ + j * 8);
                    cpa16(Ab + STG_BHI + d1, eh_ + j * 8);
                }
            }
        }
    };

    // ---- MMA over stage s ----
    auto compute_stage = [&](int s, int nks) {
        const uint32_t Ab = Sb + s * STG;
#pragma unroll
        for (int ks = 0; ks < 4; ks++) {
            if (ks >= nks) break;
            const int kb = ks * 32;
            uint32_t ahi[4][4], alo[4][4], bh[4][4];
#pragma unroll
            for (int mi = 0; mi < 4; mi++) {
                int row = m_w + mi * 16 + arow;
                uint32_t addr = Ab + (uint32_t)row * 128 +
                                ((uint32_t)(kb + ac8) ^ ((uint32_t)(row & 7) << 4));
                ldsm_x4(ahi[mi], addr + STG_AHI);
                ldsm_x4(alo[mi], addr + STG_ALO);
            }
#pragma unroll
            for (int p = 0; p < 4; p++) {  // 2 n8-tiles per x4
                int row = n_w + p * 16 + brow_base;
                uint32_t addr = Ab + STG_BHI + (uint32_t)row * 128 +
                                ((uint32_t)(kb + bk8) ^ ((uint32_t)(row & 7) << 4));
                ldsm_x4(bh[p], addr);
            }
#pragma unroll
            for (int mi = 0; mi < 4; mi++)
#pragma unroll
                for (int ni = 0; ni < 8; ni++) {
                    const uint32_t* b = &bh[ni >> 1][(ni & 1) * 2];
                    mma_f16(acc[mi][ni], ahi[mi], b);
                    mma_f16(acc[mi][ni], alo[mi], b);
                }
        }
    };

    // ---- pipelined mainloop (2-stage cp.async) ----
    load_stage(0, 0);
    cpa_commit();
    for (int ch = 0; ch < NCH; ch++) {
        if (ch + 1 < NCH) {
            load_stage(ch + 1, (ch + 1) & 1);
            cpa_commit();
            cpa_wait<1>();
        } else {
            cpa_wait<0>();
        }
        __syncthreads();
        compute_stage(ch & 1, (ch < KCH) ? 4 : 2);
        __syncthreads();
    }

    // ---- epilogue ----
    const int er = lane >> 2, ec = (lane & 3) * 2;
#pragma unroll
    for (int mi = 0; mi < 4; mi++) {
#pragma unroll
        for (int ni = 0; ni < 8; ni++) {
            float* d = acc[mi][ni];
            int gr0 = m0 + m_w + mi * 16 + er;
            int gc = n0 + n_w + ni * 8 + ec;
#pragma unroll
            for (int hrow = 0; hrow < 2; hrow++) {
                int gr = gr0 + hrow * 8;
                if (MODE == 1) {
                    float v0 = fmaxf(d[hrow * 2], 0.f), v1 = fmaxf(d[hrow * 2 + 1], 0.f);
                    __half h0 = __float2half_rn(v0), h1 = __float2half_rn(v1);
                    __half l0 = __float2half_rn(v0 - __half2float(h0));
                    __half l1 = __float2half_rn(v1 - __half2float(h1));
                    __half2 ph{h0, h1}, pl{l0, l1};
                    size_t gi = (size_t)gr * N + gc;
                    *reinterpret_cast<__half2*>(outHi + gi) = ph;
                    *reinterpret_cast<__half2*>(outLo + gi) = pl;
                } else {
                    float2 v{d[hrow * 2], d[hrow * 2 + 1]};
                    *reinterpret_cast<float2*>(outF + (size_t)gr * N + gc) = v;
                }
            }
        }
    }
}

// =============================== launch ===============================
static inline void splitF(const float* s, __half* h, __half* l, int n) {
    split_full<<<(n / 8 + 255) / 256, 256>>>(s, h, l, n);
}
static inline void splitH(const float* s, __half* h, int n) {
    split_hi<<<(n / 8 + 255) / 256, 256>>>(s, h, n);
}

extern "C" void kernel_launch(void* const* d_in, const int* in_sizes, int n_in,
                              void* d_out, int out_size)
{
    (void)in_sizes; (void)n_in; (void)out_size;
    const float* x     = (const float*)d_in[0];
    const int*   eids  = (const int*)d_in[1];
    const float* wi    = (const float*)d_in[2];
    const float* wo    = (const float*)d_in[3];
    const float* cwi_a = (const float*)d_in[4];
    const float* cwi_b = (const float*)d_in[5];
    const float* cwo_a = (const float*)d_in[6];
    const float* cwo_b = (const float*)d_in[7];
    const float* ewi_a = (const float*)d_in[8];
    const float* ewi_b = (const float*)d_in[9];
    const float* ewo_a = (const float*)d_in[10];
    const float* ewo_b = (const float*)d_in[11];
    float* out = (float*)d_out;

    __half *hhi, *hlo, *xhi, *xlo, *wihi, *wohi;
    __half *u1hi, *u1lo, *u2hi, *u2lo;
    __half *wbc1h, *wbe1h, *wbc2h, *wbe2h;
    float *U1, *U2;
    cudaGetSymbolAddress((void**)&hhi, g_hid_hi);   cudaGetSymbolAddress((void**)&hlo, g_hid_lo);
    cudaGetSymbolAddress((void**)&xhi, g_x_hi);     cudaGetSymbolAddress((void**)&xlo, g_x_lo);
    cudaGetSymbolAddress((void**)&wihi, g_wi_hi);   cudaGetSymbolAddress((void**)&wohi, g_wo_hi);
    cudaGetSymbolAddress((void**)&U1, g_U1);        cudaGetSymbolAddress((void**)&U2, g_U2);
    cudaGetSymbolAddress((void**)&u1hi, g_U1_hi);   cudaGetSymbolAddress((void**)&u1lo, g_U1_lo);
    cudaGetSymbolAddress((void**)&u2hi, g_U2_hi);   cudaGetSymbolAddress((void**)&u2lo, g_U2_lo);
    cudaGetSymbolAddress((void**)&wbc1h, g_wbc1_hi);
    cudaGetSymbolAddress((void**)&wbe1h, g_wbe1_hi);
    cudaGetSymbolAddress((void**)&wbc2h, g_wbc2_hi);
    cudaGetSymbolAddress((void**)&wbe2h, g_wbe2_hi);

    cudaFuncSetAttribute(gemm_cp<1>, cudaFuncAttributeMaxDynamicSharedMemorySize, SMEM_DYN);
    cudaFuncSetAttribute(gemm_cp<0>, cudaFuncAttributeMaxDynamicSharedMemorySize, SMEM_DYN);

    // pre-splits
    splitF(x, xhi, xlo, T_TOK * D_DIM);
    splitH(wi, wihi, F_DIM * D_DIM);
    splitH(wo, wohi, D_DIM * F_DIM);
    splitH(cwi_b, wbc1h, F_DIM * 16);
    splitH(ewi_b, wbe1h, E_EXP * F_DIM * 16);
    splitH(cwo_b, wbc2h, D_DIM * 16);
    splitH(ewo_b, wbe2h, E_EXP * D_DIM * 16);

    // stage 1
    lora_proj<0><<<T_TOK / 8, 256>>>(x, nullptr, cwi_a, ewi_a, eids, U1, D_DIM);
    splitF(U1, u1hi, u1lo, T_TOK * 32);
    dim3 g1(F_DIM / 128, T_TOK / 256);
    gemm_cp<1><<<g1, 256, SMEM_DYN>>>(xhi, xlo, wihi, u1hi, u1lo, wbc1h, wbe1h,
                                      eids, nullptr, hhi, hlo, F_DIM, D_DIM);

    // stage 2
    lora_proj<1><<<T_TOK / 8, 256>>>(nullptr, hhi, cwo_a, ewo_a, eids, U2, F_DIM);
    splitF(U2, u2hi, u2lo, T_TOK * 32);
    dim3 g2(D_DIM / 128, T_TOK / 256);
    gemm_cp<0><<<g2, 256, SMEM_DYN>>>(hhi, hlo, wohi, u2hi, u2lo, wbc2h, wbe2h,
                                      eids, out, nullptr, nullptr, D_DIM, F_DIM);
}

// round 10
// speedup vs baseline: 3.7713x; 1.6976x over previous
#include <cuda_runtime.h>
#include <cuda_fp16.h>
#include <cstdint>
#include <cstddef>

#define T_TOK 16384
#define D_DIM 1024
#define F_DIM 4096
#define E_EXP 8
#define ALPHA_F 2.0f

// ---- device scratch (allocation-free) ----
__device__ __half g_hid_hi[(size_t)T_TOK * F_DIM];   // hidden: hi only
__device__ __half g_x_hi[(size_t)T_TOK * D_DIM];
__device__ __half g_x_lo[(size_t)T_TOK * D_DIM];
__device__ __half g_wi_hi[(size_t)F_DIM * D_DIM];
__device__ __half g_wo_hi[(size_t)D_DIM * F_DIM];
__device__ float g_U1[T_TOK * 32];
__device__ float g_U2[T_TOK * 32];
__device__ __half g_U1_hi[T_TOK * 32], g_U1_lo[T_TOK * 32];
__device__ __half g_U2_hi[T_TOK * 32];
__device__ __half g_wbc1_hi[F_DIM * 16];
__device__ __half g_wbe1_hi[E_EXP * F_DIM * 16];
__device__ __half g_wbc2_hi[D_DIM * 16];
__device__ __half g_wbe2_hi[E_EXP * D_DIM * 16];

// ---------------- helpers ----------------
__device__ __forceinline__ uint32_t smem_u32(const void* p) {
    uint32_t a;
    asm("{ .reg .u64 t; cvta.to.shared.u64 t, %1; cvt.u32.u64 %0, t; }" : "=r"(a) : "l"(p));
    return a;
}
__device__ __forceinline__ void ldsm_x4(uint32_t* r, uint32_t addr) {
    asm volatile("ldmatrix.sync.aligned.m8n8.x4.shared.b16 {%0,%1,%2,%3}, [%4];"
                 : "=r"(r[0]), "=r"(r[1]), "=r"(r[2]), "=r"(r[3]) : "r"(addr));
}
__device__ __forceinline__ void mma_f16(float* d, const uint32_t* a, const uint32_t* b) {
    asm volatile(
        "mma.sync.aligned.m16n8k16.row.col.f32.f16.f16.f32 "
        "{%0,%1,%2,%3},{%4,%5,%6,%7},{%8,%9},{%0,%1,%2,%3};"
        : "+f"(d[0]), "+f"(d[1]), "+f"(d[2]), "+f"(d[3])
        : "r"(a[0]), "r"(a[1]), "r"(a[2]), "r"(a[3]), "r"(b[0]), "r"(b[1]));
}
__device__ __forceinline__ void cpa16(uint32_t dst, const void* src) {
    asm volatile("cp.async.cg.shared.global [%0], [%1], 16;" :: "r"(dst), "l"(src));
}
__device__ __forceinline__ void cpa_commit() {
    asm volatile("cp.async.commit_group;" ::: "memory");
}
template <int NW>
__device__ __forceinline__ void cpa_wait() {
    asm volatile("cp.async.wait_group %0;" :: "n"(NW) : "memory");
}

// ================ pre-pass: split fp32 -> fp16 hi(+lo) ================
__global__ __launch_bounds__(256) void split_full(
    const float* __restrict__ src, __half* __restrict__ hi,
    __half* __restrict__ lo, int n)
{
    int i = (blockIdx.x * 256 + threadIdx.x) * 8;
    if (i >= n) return;
    float a[8];
    *(float4*)&a[0] = *(const float4*)(src + i);
    *(float4*)&a[4] = *(const float4*)(src + i + 4);
    uint32_t hw[4], lw[4];
#pragma unroll
    for (int j = 0; j < 4; j++) {
        float x0 = a[2 * j], x1 = a[2 * j + 1];
        __half h0 = __float2half_rn(x0), h1 = __float2half_rn(x1);
        __half l0 = __float2half_rn(x0 - __half2float(h0));
        __half l1 = __float2half_rn(x1 - __half2float(h1));
        __half2 ph{h0, h1}, pl{l0, l1};
        hw[j] = *reinterpret_cast<uint32_t*>(&ph);
        lw[j] = *reinterpret_cast<uint32_t*>(&pl);
    }
    *(uint4*)(hi + i) = make_uint4(hw[0], hw[1], hw[2], hw[3]);
    *(uint4*)(lo + i) = make_uint4(lw[0], lw[1], lw[2], lw[3]);
}

__global__ __launch_bounds__(256) void split_hi(
    const float* __restrict__ src, __half* __restrict__ hi, int n)
{
    int i = (blockIdx.x * 256 + threadIdx.x) * 8;
    if (i >= n) return;
    float a[8];
    *(float4*)&a[0] = *(const float4*)(src + i);
    *(float4*)&a[4] = *(const float4*)(src + i + 4);
    uint32_t hw[4];
#pragma unroll
    for (int j = 0; j < 4; j++) {
        __half2 ph{__float2half_rn(a[2 * j]), __float2half_rn(a[2 * j + 1])};
        hw[j] = *reinterpret_cast<uint32_t*>(&ph);
    }
    *(uint4*)(hi + i) = make_uint4(hw[0], hw[1], hw[2], hw[3]);
}

// ================= low-rank projection (U = ALPHA * X . Wa^T) =================
template <int BF>
__global__ __launch_bounds__(256) void lora_proj(
    const float* __restrict__ Xf, const __half* __restrict__ Xhi,
    const float* __restrict__ Wa_c, const float* __restrict__ Wa_e,
    const int* __restrict__ eids, float* __restrict__ U, int K)
{
    __shared__ float xs[8][1024];
    const int tid = threadIdx.x, t0 = blockIdx.x * 8;
    const int e = eids[t0 >> 9];
    const int r = tid >> 3, sub = tid & 7;
    const float* wrow = (r < 16) ? (Wa_c + (size_t)r * K)
                                 : (Wa_e + ((size_t)e * 16 + (r - 16)) * (size_t)K);
    float acc[8];
#pragma unroll
    for (int t = 0; t < 8; t++) acc[t] = 0.f;

    for (int kc = 0; kc < K; kc += 1024) {
        __syncthreads();
        if (BF) {
#pragma unroll
            for (int i = 0; i < 4; i++) {
                int f = tid + i * 256, tt = f >> 7, c8 = f & 127;
                size_t g = (size_t)(t0 + tt) * K + kc + c8 * 8;
                uint4 h = *(const uint4*)(Xhi + g);
                const uint32_t* hw = (const uint32_t*)&h;
#pragma unroll
                for (int w = 0; w < 4; w++) {
                    float2 fh = __half22float2(*(const __half2*)&hw[w]);
                    xs[tt][c8 * 8 + w * 2] = fh.x;
                    xs[tt][c8 * 8 + w * 2 + 1] = fh.y;
                }
            }
        } else {
#pragma unroll
            for (int i = 0; i < 8; i++) {
                int f = tid + i * 256, tt = f >> 8, c4 = f & 255;
                *(float4*)&xs[tt][c4 * 4] =
                    *(const float4*)(Xf + (size_t)(t0 + tt) * K + kc + c4 * 4);
            }
        }
        __syncthreads();
        const float4* w4 = (const float4*)(wrow + kc);
#pragma unroll 4
        for (int i = 0; i < 32; i++) {
            int f = i * 8 + sub;
            float4 w = w4[f];
#pragma unroll
            for (int t = 0; t < 8; t++) {
                float4 xv = *(const float4*)&xs[t][f * 4];
                acc[t] += w.x * xv.x + w.y * xv.y + w.z * xv.z + w.w * xv.w;
            }
        }
    }
#pragma unroll
    for (int off = 4; off > 0; off >>= 1)
#pragma unroll
        for (int t = 0; t < 8; t++) acc[t] += __shfl_down_sync(0xffffffffu, acc[t], off, 8);
    if (sub == 0)
#pragma unroll
        for (int t = 0; t < 8; t++) U[(size_t)(t0 + t) * 32 + r] = ALPHA_F * acc[t];
}

// ============= fp16 GEMM + fused LoRA, 2 CTAs/SM (cp.async pipeline) =============
// CTA tile 128x128, BK=64, 8 warps @ 32x64 (acc=64 regs -> 2 CTAs/SM).
// MODE 1 (GEMM1): C = (Ahi+Alo).Bhi^T, relu, fp16-hi out. Stage: Ahi|Alo|B = 48KB.
// MODE 0 (GEMM2): C = Ahi.Bhi^T, fp32 out.               Stage: Ahi|B = 32KB.

template <int MODE>
__global__ __launch_bounds__(256, 2) void gemm_cp(
    const __half* __restrict__ Ahi, const __half* __restrict__ Alo,
    const __half* __restrict__ Bhi,
    const __half* __restrict__ Uhi, const __half* __restrict__ Ulo,
    const __half* __restrict__ Wbc_hi, const __half* __restrict__ Wbe_hi,
    const int* __restrict__ eids,
    float* __restrict__ outF, __half* __restrict__ outHi, int N, int K)
{
    constexpr uint32_t ALO_OFF = 16384;
    constexpr uint32_t B_OFF = MODE ? 32768 : 16384;
    constexpr uint32_t STG = MODE ? 49152 : 32768;

    extern __shared__ char smraw[];
    uint32_t sd0 = smem_u32(smraw);
    char* smem = smraw + (((sd0 + 1023u) & ~1023u) - sd0);
    const uint32_t Sb = smem_u32(smem);

    const int tid = threadIdx.x, wid = tid >> 5, lane = tid & 31;
    const int m0 = blockIdx.y * 128, n0 = blockIdx.x * 128;
    const int e = eids[m0 >> 9];

    const int m_w = (wid >> 1) * 32, n_w = (wid & 1) * 64;
    const int arow = lane & 15, ac8 = (lane >> 4) * 16;
    const int brow_base = ((lane >> 4) & 1) * 8 + (lane & 7);
    const int bk8 = ((lane >> 3) & 1) * 16;

    float acc[2][8][4];
#pragma unroll
    for (int i = 0; i < 2; i++)
#pragma unroll
        for (int j = 0; j < 8; j++)
#pragma unroll
            for (int q = 0; q < 4; q++) acc[i][j][q] = 0.f;

    const int KCH = K >> 6, NCH = KCH + 1;
    const int srow = tid >> 1, shf = tid & 1;   // 128 rows, 2 threads/row

    // ---- async load of chunk ch into stage s ----
    auto load_stage = [&](int ch, int s) {
        const uint32_t Ab = Sb + s * STG;
        const uint32_t ro = (uint32_t)srow * 128, xm = (uint32_t)(srow & 7) << 4;
        if (ch < KCH) {
            const int kc = ch << 6;
            {   // A rows (hi, + lo for MODE1): 64B per (row,half)
                const __half* sh = Ahi + (size_t)(m0 + srow) * K + kc + shf * 32;
#pragma unroll
                for (int j = 0; j < 4; j++) {
                    uint32_t d = ro + ((uint32_t)(shf * 64 + j * 16) ^ xm);
                    cpa16(Ab + d, sh + j * 8);
                }
                if (MODE) {
                    const __half* sl = Alo + (size_t)(m0 + srow) * K + kc + shf * 32;
#pragma unroll
                    for (int j = 0; j < 4; j++) {
                        uint32_t d = ro + ((uint32_t)(shf * 64 + j * 16) ^ xm);
                        cpa16(Ab + ALO_OFF + d, sl + j * 8);
                    }
                }
            }
            {   // B rows
                const __half* sh = Bhi + (size_t)(n0 + srow) * K + kc + shf * 32;
#pragma unroll
                for (int j = 0; j < 4; j++) {
                    uint32_t d = ro + ((uint32_t)(shf * 64 + j * 16) ^ xm);
                    cpa16(Ab + B_OFF + d, sh + j * 8);
                }
            }
        } else {
            {   // A-lora: U rows (32 fp16 = 64B); each thread 32B
                const __half* sh = Uhi + (size_t)(m0 + srow) * 32 + shf * 16;
#pragma unroll
                for (int j = 0; j < 2; j++) {
                    uint32_t d = ro + ((uint32_t)(shf * 32 + j * 16) ^ xm);
                    cpa16(Ab + d, sh + j * 8);
                }
                if (MODE) {
                    const __half* sl = Ulo + (size_t)(m0 + srow) * 32 + shf * 16;
#pragma unroll
                    for (int j = 0; j < 2; j++) {
                        uint32_t d = ro + ((uint32_t)(shf * 32 + j * 16) ^ xm);
                        cpa16(Ab + ALO_OFF + d, sl + j * 8);
                    }
                }
            }
            {   // B-lora: k 0:16 = Wbc (hf=0), 16:32 = Wbe[e] (hf=1)
                const __half* sb = shf
                    ? (Wbe_hi + (size_t)e * N * 16 + (size_t)(n0 + srow) * 16)
                    : (Wbc_hi + (size_t)(n0 + srow) * 16);
#pragma unroll
                for (int j = 0; j < 2; j++) {
                    uint32_t d = ro + ((uint32_t)(shf * 32 + j * 16) ^ xm);
                    cpa16(Ab + B_OFF + d, sb + j * 8);
                }
            }
        }
    };

    // ---- MMA over stage s ----
    auto compute_stage = [&](int s, int nks) {
        const uint32_t Ab = Sb + s * STG;
#pragma unroll
        for (int ks = 0; ks < 4; ks++) {
            if (ks >= nks) break;
            const int kb = ks * 32;
            uint32_t ahi[2][4], alo[2][4], bh[4][4];
#pragma unroll
            for (int mi = 0; mi < 2; mi++) {
                int row = m_w + mi * 16 + arow;
                uint32_t addr = Ab + (uint32_t)row * 128 +
                                ((uint32_t)(kb + ac8) ^ ((uint32_t)(row & 7) << 4));
                ldsm_x4(ahi[mi], addr);
                if (MODE) ldsm_x4(alo[mi], addr + ALO_OFF);
            }
#pragma unroll
            for (int p = 0; p < 4; p++) {
                int row = n_w + p * 16 + brow_base;
                uint32_t addr = Ab + B_OFF + (uint32_t)row * 128 +
                                ((uint32_t)(kb + bk8) ^ ((uint32_t)(row & 7) << 4));
                ldsm_x4(bh[p], addr);
            }
#pragma unroll
            for (int mi = 0; mi < 2; mi++)
#pragma unroll
                for (int ni = 0; ni < 8; ni++) {
                    const uint32_t* b = &bh[ni >> 1][(ni & 1) * 2];
                    mma_f16(acc[mi][ni], ahi[mi], b);
                    if (MODE) mma_f16(acc[mi][ni], alo[mi], b);
                }
        }
    };

    // ---- pipelined mainloop (2-stage cp.async) ----
    load_stage(0, 0);
    cpa_commit();
    for (int ch = 0; ch < NCH; ch++) {
        if (ch + 1 < NCH) {
            load_stage(ch + 1, (ch + 1) & 1);
            cpa_commit();
            cpa_wait<1>();
        } else {
            cpa_wait<0>();
        }
        __syncthreads();
        compute_stage(ch & 1, (ch < KCH) ? 4 : 2);
        __syncthreads();
    }

    // ---- epilogue ----
    const int er = lane >> 2, ec = (lane & 3) * 2;
#pragma unroll
    for (int mi = 0; mi < 2; mi++) {
#pragma unroll
        for (int ni = 0; ni < 8; ni++) {
            float* d = acc[mi][ni];
            int gr0 = m0 + m_w + mi * 16 + er;
            int gc = n0 + n_w + ni * 8 + ec;
#pragma unroll
            for (int hrow = 0; hrow < 2; hrow++) {
                int gr = gr0 + hrow * 8;
                if (MODE == 1) {
                    float v0 = fmaxf(d[hrow * 2], 0.f), v1 = fmaxf(d[hrow * 2 + 1], 0.f);
                    __half2 ph{__float2half_rn(v0), __float2half_rn(v1)};
                    *reinterpret_cast<__half2*>(outHi + (size_t)gr * N + gc) = ph;
                } else {
                    float2 v{d[hrow * 2], d[hrow * 2 + 1]};
                    *reinterpret_cast<float2*>(outF + (size_t)gr * N + gc) = v;
                }
            }
        }
    }
}

// =============================== launch ===============================
static inline void splitF(const float* s, __half* h, __half* l, int n) {
    split_full<<<(n / 8 + 255) / 256, 256>>>(s, h, l, n);
}
static inline void splitH(const float* s, __half* h, int n) {
    split_hi<<<(n / 8 + 255) / 256, 256>>>(s, h, n);
}

extern "C" void kernel_launch(void* const* d_in, const int* in_sizes, int n_in,
                              void* d_out, int out_size)
{
    (void)in_sizes; (void)n_in; (void)out_size;
    const float* x     = (const float*)d_in[0];
    const int*   eids  = (const int*)d_in[1];
    const float* wi    = (const float*)d_in[2];
    const float* wo    = (const float*)d_in[3];
    const float* cwi_a = (const float*)d_in[4];
    const float* cwi_b = (const float*)d_in[5];
    const float* cwo_a = (const float*)d_in[6];
    const float* cwo_b = (const float*)d_in[7];
    const float* ewi_a = (const float*)d_in[8];
    const float* ewi_b = (const float*)d_in[9];
    const float* ewo_a = (const float*)d_in[10];
    const float* ewo_b = (const float*)d_in[11];
    float* out = (float*)d_out;

    __half *hhi, *xhi, *xlo, *wihi, *wohi;
    __half *u1hi, *u1lo, *u2hi;
    __half *wbc1h, *wbe1h, *wbc2h, *wbe2h;
    float *U1, *U2;
    cudaGetSymbolAddress((void**)&hhi, g_hid_hi);
    cudaGetSymbolAddress((void**)&xhi, g_x_hi);     cudaGetSymbolAddress((void**)&xlo, g_x_lo);
    cudaGetSymbolAddress((void**)&wihi, g_wi_hi);   cudaGetSymbolAddress((void**)&wohi, g_wo_hi);
    cudaGetSymbolAddress((void**)&U1, g_U1);        cudaGetSymbolAddress((void**)&U2, g_U2);
    cudaGetSymbolAddress((void**)&u1hi, g_U1_hi);   cudaGetSymbolAddress((void**)&u1lo, g_U1_lo);
    cudaGetSymbolAddress((void**)&u2hi, g_U2_hi);
    cudaGetSymbolAddress((void**)&wbc1h, g_wbc1_hi);
    cudaGetSymbolAddress((void**)&wbe1h, g_wbe1_hi);
    cudaGetSymbolAddress((void**)&wbc2h, g_wbc2_hi);
    cudaGetSymbolAddress((void**)&wbe2h, g_wbe2_hi);

    const int SMEM1 = 2 * 49152 + 1024;
    const int SMEM0 = 2 * 32768 + 1024;
    cudaFuncSetAttribute(gemm_cp<1>, cudaFuncAttributeMaxDynamicSharedMemorySize, SMEM1);
    cudaFuncSetAttribute(gemm_cp<0>, cudaFuncAttributeMaxDynamicSharedMemorySize, SMEM0);

    // pre-splits
    splitF(x, xhi, xlo, T_TOK * D_DIM);
    splitH(wi, wihi, F_DIM * D_DIM);
    splitH(wo, wohi, D_DIM * F_DIM);
    splitH(cwi_b, wbc1h, F_DIM * 16);
    splitH(ewi_b, wbe1h, E_EXP * F_DIM * 16);
    splitH(cwo_b, wbc2h, D_DIM * 16);
    splitH(ewo_b, wbe2h, E_EXP * D_DIM * 16);

    // stage 1: hidden_hi = relu(x@wi^T + lora)
    lora_proj<0><<<T_TOK / 8, 256>>>(x, nullptr, cwi_a, ewi_a, eids, U1, D_DIM);
    splitF(U1, u1hi, u1lo, T_TOK * 32);
    dim3 g1(F_DIM / 128, T_TOK / 128);
    gemm_cp<1><<<g1, 256, SMEM1>>>(xhi, xlo, wihi, u1hi, u1lo, wbc1h, wbe1h,
                                   eids, nullptr, hhi, F_DIM, D_DIM);

    // stage 2: out = hidden@wo^T + lora (single product)
    lora_proj<1><<<T_TOK / 8, 256>>>(nullptr, hhi, cwo_a, ewo_a, eids, U2, F_DIM);
    splitH(U2, u2hi, T_TOK * 32);
    dim3 g2(D_DIM / 128, T_TOK / 128);
    gemm_cp<0><<<g2, 256, SMEM0>>>(hhi, nullptr, wohi, u2hi, nullptr, wbc2h, wbe2h,
                                   eids, out, nullptr, D_DIM, F_DIM);
}

// round 11
// speedup vs baseline: 6.6085x; 1.7523x over previous
#include <cuda_runtime.h>
#include <cuda_fp16.h>
#include <cstdint>
#include <cstddef>

#define T_TOK 16384
#define D_DIM 1024
#define F_DIM 4096
#define E_EXP 8
#define ALPHA_F 2.0f

// ---- device scratch (allocation-free; all fp16 hi-only) ----
__device__ __half g_hid[(size_t)T_TOK * F_DIM];
__device__ __half g_x[(size_t)T_TOK * D_DIM];
__device__ __half g_wi[(size_t)F_DIM * D_DIM];
__device__ __half g_wo[(size_t)D_DIM * F_DIM];
__device__ __half g_U1[T_TOK * 32];
__device__ __half g_U2[T_TOK * 32];
__device__ __half g_wbc1[F_DIM * 16];
__device__ __half g_wbe1[E_EXP * F_DIM * 16];
__device__ __half g_wbc2[D_DIM * 16];
__device__ __half g_wbe2[E_EXP * D_DIM * 16];
__device__ __half g_wac1[16 * D_DIM];
__device__ __half g_wae1[E_EXP * 16 * D_DIM];
__device__ __half g_wac2[16 * F_DIM];
__device__ __half g_wae2[E_EXP * 16 * F_DIM];

// ---------------- helpers ----------------
__device__ __forceinline__ uint32_t smem_u32(const void* p) {
    uint32_t a;
    asm("{ .reg .u64 t; cvta.to.shared.u64 t, %1; cvt.u32.u64 %0, t; }" : "=r"(a) : "l"(p));
    return a;
}
__device__ __forceinline__ void ldsm_x4(uint32_t* r, uint32_t addr) {
    asm volatile("ldmatrix.sync.aligned.m8n8.x4.shared.b16 {%0,%1,%2,%3}, [%4];"
                 : "=r"(r[0]), "=r"(r[1]), "=r"(r[2]), "=r"(r[3]) : "r"(addr));
}
__device__ __forceinline__ void mma_f16(float* d, const uint32_t* a, const uint32_t* b) {
    asm volatile(
        "mma.sync.aligned.m16n8k16.row.col.f32.f16.f16.f32 "
        "{%0,%1,%2,%3},{%4,%5,%6,%7},{%8,%9},{%0,%1,%2,%3};"
        : "+f"(d[0]), "+f"(d[1]), "+f"(d[2]), "+f"(d[3])
        : "r"(a[0]), "r"(a[1]), "r"(a[2]), "r"(a[3]), "r"(b[0]), "r"(b[1]));
}
__device__ __forceinline__ void cpa16(uint32_t dst, const void* src) {
    asm volatile("cp.async.cg.shared.global [%0], [%1], 16;" :: "r"(dst), "l"(src));
}
__device__ __forceinline__ void cpa_commit() {
    asm volatile("cp.async.commit_group;" ::: "memory");
}
template <int NW>
__device__ __forceinline__ void cpa_wait() {
    asm volatile("cp.async.wait_group %0;" :: "n"(NW) : "memory");
}

// ================ pre-pass: fp32 -> fp16 ================
__global__ __launch_bounds__(256) void split_hi(
    const float* __restrict__ src, __half* __restrict__ hi, int n)
{
    int i = (blockIdx.x * 256 + threadIdx.x) * 8;
    if (i >= n) return;
    float a[8];
    *(float4*)&a[0] = *(const float4*)(src + i);
    *(float4*)&a[4] = *(const float4*)(src + i + 4);
    uint32_t hw[4];
#pragma unroll
    for (int j = 0; j < 4; j++) {
        __half2 ph{__float2half_rn(a[2 * j]), __float2half_rn(a[2 * j + 1])};
        hw[j] = *reinterpret_cast<uint32_t*>(&ph);
    }
    *(uint4*)(hi + i) = make_uint4(hw[0], hw[1], hw[2], hw[3]);
}

// ============ skinny HMMA lora GEMM: U = ALPHA * X @ [Wac;Wae[e]]^T ============
// CTA: 64 rows x 32 cols, 128 threads (4 warps @ 16x32). BK=64, 2-stage.
#define LSTG 12288
#define LB_OFF 8192

__global__ __launch_bounds__(128) void lora_gemm(
    const __half* __restrict__ X, const __half* __restrict__ Wac,
    const __half* __restrict__ Wae, const int* __restrict__ eids,
    __half* __restrict__ U, int K)
{
    extern __shared__ char smraw[];
    uint32_t sd0 = smem_u32(smraw);
    char* smem = smraw + (((sd0 + 1023u) & ~1023u) - sd0);
    const uint32_t Sb = smem_u32(smem);

    const int tid = threadIdx.x, wid = tid >> 5, lane = tid & 31;
    const int m0 = blockIdx.x * 64;
    const int e = eids[m0 >> 9];
    const int m_w = wid * 16;

    const int arow = lane & 15, ac8 = (lane >> 4) * 16;
    const int brow_base = ((lane >> 4) & 1) * 8 + (lane & 7);
    const int bk8 = ((lane >> 3) & 1) * 16;

    float acc[4][4];
#pragma unroll
    for (int i = 0; i < 4; i++)
#pragma unroll
        for (int q = 0; q < 4; q++) acc[i][q] = 0.f;

    const int KCH = K >> 6;
    const int srow = tid >> 1, shf = tid & 1;

    auto load_stage = [&](int ch, int s) {
        const uint32_t Ab = Sb + s * LSTG;
        const int kc = ch << 6;
        {   // A: 64 rows x 128B
            const __half* sh = X + (size_t)(m0 + srow) * K + kc + shf * 32;
            const uint32_t ro = (uint32_t)srow * 128, xm = (uint32_t)(srow & 7) << 4;
#pragma unroll
            for (int j = 0; j < 4; j++)
                cpa16(Ab + ro + (((uint32_t)(shf * 64 + j * 16)) ^ xm), sh + j * 8);
        }
        if (tid < 64) {  // B: 32 rows (16 common + 16 expert) x 128B
            const int row = tid >> 1, bhf = tid & 1;
            const __half* sb = (row < 16)
                ? (Wac + (size_t)row * K + kc + bhf * 32)
                : (Wae + ((size_t)e * 16 + (row - 16)) * (size_t)K + kc + bhf * 32);
            const uint32_t ro = (uint32_t)row * 128, xm = (uint32_t)(row & 7) << 4;
#pragma unroll
            for (int j = 0; j < 4; j++)
                cpa16(Ab + LB_OFF + ro + (((uint32_t)(bhf * 64 + j * 16)) ^ xm), sb + j * 8);
        }
    };

    auto compute_stage = [&](int s) {
        const uint32_t Ab = Sb + s * LSTG;
#pragma unroll
        for (int ks = 0; ks < 4; ks++) {
            const int kb = ks * 32;
            uint32_t ah[4], bh[2][4];
            {
                int row = m_w + arow;
                ldsm_x4(ah, Ab + (uint32_t)row * 128 +
                            ((uint32_t)(kb + ac8) ^ ((uint32_t)(row & 7) << 4)));
            }
#pragma unroll
            for (int p = 0; p < 2; p++) {
                int row = p * 16 + brow_base;
                ldsm_x4(bh[p], Ab + LB_OFF + (uint32_t)row * 128 +
                               ((uint32_t)(kb + bk8) ^ ((uint32_t)(row & 7) << 4)));
            }
#pragma unroll
            for (int ni = 0; ni < 4; ni++)
                mma_f16(acc[ni], ah, &bh[ni >> 1][(ni & 1) * 2]);
        }
    };

    load_stage(0, 0);
    cpa_commit();
    for (int ch = 0; ch < KCH; ch++) {
        if (ch + 1 < KCH) {
            load_stage(ch + 1, (ch + 1) & 1);
            cpa_commit();
            cpa_wait<1>();
        } else {
            cpa_wait<0>();
        }
        __syncthreads();
        compute_stage(ch & 1);
        __syncthreads();
    }

    const int er = lane >> 2, ec = (lane & 3) * 2;
#pragma unroll
    for (int ni = 0; ni < 4; ni++) {
#pragma unroll
        for (int hrow = 0; hrow < 2; hrow++) {
            int gr = m0 + m_w + er + hrow * 8;
            int gc = ni * 8 + ec;
            __half2 v{__float2half_rn(ALPHA_F * acc[ni][hrow * 2]),
                      __float2half_rn(ALPHA_F * acc[ni][hrow * 2 + 1])};
            *reinterpret_cast<__half2*>(U + (size_t)gr * 32 + gc) = v;
        }
    }
}

// ========== single-product fp16 GEMM + fused LoRA, 3-stage pipeline ==========
// CTA 128x128, BK=64, 8 warps @ 32x64, 2 CTAs/SM. Stage: A 16K | B 16K = 32KB x3.
#define GSTG 32768
#define GB_OFF 16384
#define GSMEM (3 * GSTG + 1024)

template <int MODE>  // 1: relu -> fp16 out; 0: fp32 out
__global__ __launch_bounds__(256, 2) void gemm_cp(
    const __half* __restrict__ A, const __half* __restrict__ B,
    const __half* __restrict__ U,
    const __half* __restrict__ Wbc, const __half* __restrict__ Wbe,
    const int* __restrict__ eids,
    float* __restrict__ outF, __half* __restrict__ outH, int N, int K)
{
    extern __shared__ char smraw[];
    uint32_t sd0 = smem_u32(smraw);
    char* smem = smraw + (((sd0 + 1023u) & ~1023u) - sd0);
    const uint32_t Sb = smem_u32(smem);

    const int tid = threadIdx.x, wid = tid >> 5, lane = tid & 31;
    const int m0 = blockIdx.y * 128, n0 = blockIdx.x * 128;
    const int e = eids[m0 >> 9];

    const int m_w = (wid >> 1) * 32, n_w = (wid & 1) * 64;
    const int arow = lane & 15, ac8 = (lane >> 4) * 16;
    const int brow_base = ((lane >> 4) & 1) * 8 + (lane & 7);
    const int bk8 = ((lane >> 3) & 1) * 16;

    float acc[2][8][4];
#pragma unroll
    for (int i = 0; i < 2; i++)
#pragma unroll
        for (int j = 0; j < 8; j++)
#pragma unroll
            for (int q = 0; q < 4; q++) acc[i][j][q] = 0.f;

    const int KCH = K >> 6, NCH = KCH + 1;
    const int srow = tid >> 1, shf = tid & 1;

    auto load_stage = [&](int ch, int s) {
        const uint32_t Ab = Sb + (uint32_t)s * GSTG;
        const uint32_t ro = (uint32_t)srow * 128, xm = (uint32_t)(srow & 7) << 4;
        if (ch < KCH) {
            const int kc = ch << 6;
            const __half* sa = A + (size_t)(m0 + srow) * K + kc + shf * 32;
            const __half* sb = B + (size_t)(n0 + srow) * K + kc + shf * 32;
#pragma unroll
            for (int j = 0; j < 4; j++) {
                uint32_t d = ((uint32_t)(shf * 64 + j * 16)) ^ xm;
                cpa16(Ab + ro + d, sa + j * 8);
                cpa16(Ab + GB_OFF + ro + d, sb + j * 8);
            }
        } else {
            // lora chunk: A = U[m,0:32]; B k 0:16 = Wbc, 16:32 = Wbe[e]
            const __half* su = U + (size_t)(m0 + srow) * 32 + shf * 16;
            const __half* sb = shf
                ? (Wbe + (size_t)e * N * 16 + (size_t)(n0 + srow) * 16)
                : (Wbc + (size_t)(n0 + srow) * 16);
#pragma unroll
            for (int j = 0; j < 2; j++) {
                uint32_t d = ((uint32_t)(shf * 32 + j * 16)) ^ xm;
                cpa16(Ab + ro + d, su + j * 8);
                cpa16(Ab + GB_OFF + ro + d, sb + j * 8);
            }
        }
    };

    auto compute_stage = [&](int s, int nks) {
        const uint32_t Ab = Sb + (uint32_t)s * GSTG;
#pragma unroll
        for (int ks = 0; ks < 4; ks++) {
            if (ks >= nks) break;
            const int kb = ks * 32;
            uint32_t ah[2][4], bh[4][4];
#pragma unroll
            for (int mi = 0; mi < 2; mi++) {
                int row = m_w + mi * 16 + arow;
                ldsm_x4(ah[mi], Ab + (uint32_t)row * 128 +
                                ((uint32_t)(kb + ac8) ^ ((uint32_t)(row & 7) << 4)));
            }
#pragma unroll
            for (int p = 0; p < 4; p++) {
                int row = n_w + p * 16 + brow_base;
                ldsm_x4(bh[p], Ab + GB_OFF + (uint32_t)row * 128 +
                               ((uint32_t)(kb + bk8) ^ ((uint32_t)(row & 7) << 4)));
            }
#pragma unroll
            for (int mi = 0; mi < 2; mi++)
#pragma unroll
                for (int ni = 0; ni < 8; ni++)
                    mma_f16(acc[mi][ni], ah[mi], &bh[ni >> 1][(ni & 1) * 2]);
        }
    };

    // ---- 3-stage pipeline, one sync per chunk ----
    load_stage(0, 0);
    cpa_commit();
    load_stage(1, 1);
    cpa_commit();
    int s3 = 0;           // stage of chunk ch (mod 3)
    for (int ch = 0; ch < NCH; ch++) {
        if (ch + 1 < NCH) cpa_wait<1>();
        else cpa_wait<0>();
        __syncthreads();
        compute_stage(s3, (ch < KCH) ? 4 : 2);
        if (ch + 2 < NCH) {
            int sn = s3 + 2;
            if (sn >= 3) sn -= 3;
            load_stage(ch + 2, sn);
            cpa_commit();
        }
        if (++s3 == 3) s3 = 0;
    }

    // ---- epilogue ----
    const int er = lane >> 2, ec = (lane & 3) * 2;
#pragma unroll
    for (int mi = 0; mi < 2; mi++) {
#pragma unroll
        for (int ni = 0; ni < 8; ni++) {
            float* d = acc[mi][ni];
            int gr0 = m0 + m_w + mi * 16 + er;
            int gc = n0 + n_w + ni * 8 + ec;
#pragma unroll
            for (int hrow = 0; hrow < 2; hrow++) {
                int gr = gr0 + hrow * 8;
                if (MODE == 1) {
                    float v0 = fmaxf(d[hrow * 2], 0.f), v1 = fmaxf(d[hrow * 2 + 1], 0.f);
                    __half2 ph{__float2half_rn(v0), __float2half_rn(v1)};
                    *reinterpret_cast<__half2*>(outH + (size_t)gr * N + gc) = ph;
                } else {
                    float2 v{d[hrow * 2], d[hrow * 2 + 1]};
                    *reinterpret_cast<float2*>(outF + (size_t)gr * N + gc) = v;
                }
            }
        }
    }
}

// =============================== launch ===============================
static inline void splitH(const float* s, __half* h, int n) {
    split_hi<<<(n / 8 + 255) / 256, 256>>>(s, h, n);
}
template <typename T> static inline T* sym(const void* s) {
    void* p; cudaGetSymbolAddress(&p, s); return (T*)p;
}

extern "C" void kernel_launch(void* const* d_in, const int* in_sizes, int n_in,
                              void* d_out, int out_size)
{
    (void)in_sizes; (void)n_in; (void)out_size;
    const float* x     = (const float*)d_in[0];
    const int*   eids  = (const int*)d_in[1];
    const float* wi    = (const float*)d_in[2];
    const float* wo    = (const float*)d_in[3];
    const float* cwi_a = (const float*)d_in[4];
    const float* cwi_b = (const float*)d_in[5];
    const float* cwo_a = (const float*)d_in[6];
    const float* cwo_b = (const float*)d_in[7];
    const float* ewi_a = (const float*)d_in[8];
    const float* ewi_b = (const float*)d_in[9];
    const float* ewo_a = (const float*)d_in[10];
    const float* ewo_b = (const float*)d_in[11];
    float* out = (float*)d_out;

    __half *hid, *xh, *wih, *woh, *U1, *U2;
    __half *wbc1, *wbe1, *wbc2, *wbe2, *wac1, *wae1, *wac2, *wae2;
    cudaGetSymbolAddress((void**)&hid, g_hid);
    cudaGetSymbolAddress((void**)&xh, g_x);
    cudaGetSymbolAddress((void**)&wih, g_wi);
    cudaGetSymbolAddress((void**)&woh, g_wo);
    cudaGetSymbolAddress((void**)&U1, g_U1);
    cudaGetSymbolAddress((void**)&U2, g_U2);
    cudaGetSymbolAddress((void**)&wbc1, g_wbc1);
    cudaGetSymbolAddress((void**)&wbe1, g_wbe1);
    cudaGetSymbolAddress((void**)&wbc2, g_wbc2);
    cudaGetSymbolAddress((void**)&wbe2, g_wbe2);
    cudaGetSymbolAddress((void**)&wac1, g_wac1);
    cudaGetSymbolAddress((void**)&wae1, g_wae1);
    cudaGetSymbolAddress((void**)&wac2, g_wac2);
    cudaGetSymbolAddress((void**)&wae2, g_wae2);

    cudaFuncSetAttribute(gemm_cp<1>, cudaFuncAttributeMaxDynamicSharedMemorySize, GSMEM);
    cudaFuncSetAttribute(gemm_cp<0>, cudaFuncAttributeMaxDynamicSharedMemorySize, GSMEM);
    const int LSMEM = 2 * LSTG + 1024;
    cudaFuncSetAttribute(lora_gemm, cudaFuncAttributeMaxDynamicSharedMemorySize, LSMEM);

    // pre-splits (all fp16 hi)
    splitH(x, xh, T_TOK * D_DIM);
    splitH(wi, wih, F_DIM * D_DIM);
    splitH(wo, woh, D_DIM * F_DIM);
    splitH(cwi_b, wbc1, F_DIM * 16);
    splitH(ewi_b, wbe1, E_EXP * F_DIM * 16);
    splitH(cwo_b, wbc2, D_DIM * 16);
    splitH(ewo_b, wbe2, E_EXP * D_DIM * 16);
    splitH(cwi_a, wac1, 16 * D_DIM);
    splitH(ewi_a, wae1, E_EXP * 16 * D_DIM);
    splitH(cwo_a, wac2, 16 * F_DIM);
    splitH(ewo_a, wae2, E_EXP * 16 * F_DIM);

    // stage 1
    lora_gemm<<<T_TOK / 64, 128, LSMEM>>>(xh, wac1, wae1, eids, U1, D_DIM);
    dim3 g1(F_DIM / 128, T_TOK / 128);
    gemm_cp<1><<<g1, 256, GSMEM>>>(xh, wih, U1, wbc1, wbe1, eids,
                                   nullptr, hid, F_DIM, D_DIM);

    // stage 2
    lora_gemm<<<T_TOK / 64, 128, LSMEM>>>(hid, wac2, wae2, eids, U2, F_DIM);
    dim3 g2(D_DIM / 128, T_TOK / 128);
    gemm_cp<0><<<g2, 256, GSMEM>>>(hid, woh, U2, wbc2, wbe2, eids,
                                   out, nullptr, D_DIM, F_DIM);
}